// round 8
// baseline (speedup 1.0000x reference)
#include <cuda_runtime.h>
#include <cuda_bf16.h>
#include <math.h>
#include <stdint.h>

#define NTOK 4096   // B*S
#define HDIM 1024
#define IDIM 4096
#define NS   128
#define TOPK 16
#define BN_EPS 1e-5f

typedef __nv_bfloat16 bf16;

// ================= scratch (static device allocations) =================
__device__ float g_rx[NTOK * NS];
__device__ float g_ry[NTOK * NS];
__device__ float g_mean[2 * NS];
__device__ float g_rstd[2 * NS];
__device__ int   g_idx[NTOK * TOPK];
__device__ float g_wk[NTOK * TOPK];
__device__ float g_eout[(size_t)NTOK * HDIM];
// bf16 split operands
__device__ bf16 g_xh[NTOK * HDIM],  g_xl[NTOK * HDIM];
__device__ bf16 g_gwh[IDIM * HDIM], g_gwl[IDIM * HDIM];
__device__ bf16 g_uwh[IDIM * HDIM], g_uwl[IDIM * HDIM];
__device__ bf16 g_dwh[HDIM * IDIM], g_dwl[HDIM * IDIM];
__device__ bf16 g_rwxh[NS * HDIM], g_rwxl[NS * HDIM];
__device__ bf16 g_rwyh[NS * HDIM], g_rwyl[NS * HDIM];
__device__ bf16 g_hh[(size_t)NTOK * IDIM], g_hl[(size_t)NTOK * IDIM];

// ================= helpers =================
__device__ __forceinline__ uint32_t smem_to_u32(const void* p) {
    uint32_t a;
    asm("{ .reg .u64 t; cvta.to.shared.u64 t, %1; cvt.u32.u64 %0, t; }" : "=r"(a) : "l"(p));
    return a;
}

#define MMA16816(c, a, b) \
    asm volatile("mma.sync.aligned.m16n8k16.row.col.f32.bf16.bf16.f32 " \
        "{%0,%1,%2,%3}, {%4,%5,%6,%7}, {%8,%9}, {%0,%1,%2,%3};" \
        : "+f"((c)[0]), "+f"((c)[1]), "+f"((c)[2]), "+f"((c)[3]) \
        : "r"((a)[0]), "r"((a)[1]), "r"((a)[2]), "r"((a)[3]), "r"((b)[0]), "r"((b)[1]))

#define LDSM_X4(r, addr) \
    asm volatile("ldmatrix.sync.aligned.m8n8.x4.shared.b16 {%0,%1,%2,%3}, [%4];" \
        : "=r"((r)[0]), "=r"((r)[1]), "=r"((r)[2]), "=r"((r)[3]) : "r"(addr))

#define TILE_B 10240   // 128 rows * 80B (32 bf16 + 8B pad), conflict-free for ldmatrix

// ================= single GEMM: 256 thr, 2-stage, 2 CTAs/SM =================
// C[M,N(128)] = (Ah+Al)[M,K] * (Bh+Bl)[N,K]^T, fp32 accum (bf16x3).
// 8 warps (2x4), warp tile 64x32. MODE 0: Cout=acc. MODE 2: Cout=acc+E.
#define S2_STAGE (4 * TILE_B)   // 40960 B per stage; 2 stages = 80 KB -> 2 CTAs/SM

template<int MODE>
__global__ __launch_bounds__(256, 2) void mma_gemm_s(
    const bf16* __restrict__ Ah, const bf16* __restrict__ Al,
    const bf16* __restrict__ Bh, const bf16* __restrict__ Bl,
    const float* __restrict__ E, float* __restrict__ Cout, int K, int ldo)
{
    extern __shared__ __align__(128) char smem[];
    const uint32_t sb = smem_to_u32(smem);
    const int tid = threadIdx.x;
    const int lane = tid & 31;
    const int warp = tid >> 5;
    const int warp_m = warp >> 2;      // 0..1
    const int warp_n = warp & 3;       // 0..3
    const int bm = blockIdx.y * 128, bn = blockIdx.x * 128;
    const int KC = K >> 5;

    float acc[4][4][4];
#pragma unroll
    for (int i = 0; i < 4; i++)
#pragma unroll
        for (int j = 0; j < 4; j++)
#pragma unroll
            for (int e = 0; e < 4; e++) acc[i][j][e] = 0.f;

    auto load_stage = [&](int st, int k0) {
#pragma unroll
        for (int j = 0; j < 8; j++) {
            const int t = j >> 1;
            int rem = tid + (j & 1) * 256;
            int r = rem >> 2, c = rem & 3;
            uint32_t sa = sb + st * S2_STAGE + t * TILE_B + r * 80 + c * 16;
            const bf16* src = (t == 0) ? Ah : (t == 1) ? Al : (t == 2) ? Bh : Bl;
            int row0 = (t < 2) ? bm : bn;
            const bf16* ga = src + (size_t)(row0 + r) * K + k0 + c * 8;
            asm volatile("cp.async.cg.shared.global [%0], [%1], 16;" :: "r"(sa), "l"(ga));
        }
    };

    load_stage(0, 0);
    asm volatile("cp.async.commit_group;" ::: "memory");

    for (int kc = 0; kc < KC; kc++) {
        asm volatile("cp.async.wait_group 0;" ::: "memory");
        __syncthreads();
        if (kc + 1 < KC) {
            load_stage((kc + 1) & 1, (kc + 1) * 32);
            asm volatile("cp.async.commit_group;" ::: "memory");
        }

        const uint32_t stage = sb + (kc & 1) * S2_STAGE;
#pragma unroll
        for (int kk = 0; kk < 32; kk += 16) {
            uint32_t ah[4][4], al[4][4], bh[4][2], bl[4][2];
#pragma unroll
            for (int fm = 0; fm < 4; fm++) {
                int row = warp_m * 64 + fm * 16 + (lane & 15);
                int kw = kk + (lane >> 4) * 8;
                uint32_t a_addr = stage + row * 80 + kw * 2;
                LDSM_X4(ah[fm], a_addr);
                LDSM_X4(al[fm], a_addr + TILE_B);
            }
#pragma unroll
            for (int fp = 0; fp < 2; fp++) {
                int row = warp_n * 32 + fp * 16 + (lane & 15);
                int kw = kk + (lane >> 4) * 8;
                uint32_t b_addr = stage + 2 * TILE_B + row * 80 + kw * 2;
                uint32_t th[4], tl[4];
                LDSM_X4(th, b_addr);
                LDSM_X4(tl, b_addr + TILE_B);
                bh[2 * fp][0] = th[0]; bh[2 * fp + 1][0] = th[1];
                bh[2 * fp][1] = th[2]; bh[2 * fp + 1][1] = th[3];
                bl[2 * fp][0] = tl[0]; bl[2 * fp + 1][0] = tl[1];
                bl[2 * fp][1] = tl[2]; bl[2 * fp + 1][1] = tl[3];
            }
#pragma unroll
            for (int fm = 0; fm < 4; fm++)
#pragma unroll
                for (int fn = 0; fn < 4; fn++) {
                    MMA16816(acc[fm][fn], ah[fm], bh[fn]);
                    MMA16816(acc[fm][fn], ah[fm], bl[fn]);
                    MMA16816(acc[fm][fn], al[fm], bh[fn]);
                }
        }
    }

#pragma unroll
    for (int fm = 0; fm < 4; fm++)
#pragma unroll
        for (int fn = 0; fn < 4; fn++) {
            int row = bm + warp_m * 64 + fm * 16 + (lane >> 2);
            int col = bn + warp_n * 32 + fn * 8 + 2 * (lane & 3);
#pragma unroll
            for (int h = 0; h < 2; h++) {
                int r = row + h * 8;
                size_t off = (size_t)r * ldo + col;
                float d0 = acc[fm][fn][2 * h], d1 = acc[fm][fn][2 * h + 1];
                if (MODE == 2) {
                    float2 e = *(const float2*)(E + off);
                    d0 += e.x; d1 += e.y;
                }
                *(float2*)(Cout + off) = make_float2(d0, d1);
            }
        }
}

// ================= DUAL gate+up GEMM (512 thr, 3-stage) =================
#define D_STAGE (6 * TILE_B)
#define D_NSTAGE 3

__global__ __launch_bounds__(512, 1) void mma_gemm_dual(
    const bf16* __restrict__ Ah, const bf16* __restrict__ Al,
    const bf16* __restrict__ B1h, const bf16* __restrict__ B1l,
    const bf16* __restrict__ B2h, const bf16* __restrict__ B2l,
    bf16* __restrict__ Hh, bf16* __restrict__ Hl, int K, int ldo)
{
    extern __shared__ __align__(128) char smem[];
    const uint32_t sb = smem_to_u32(smem);
    const int tid = threadIdx.x;
    const int lane = tid & 31;
    const int warp = tid >> 5;
    const int warp_m = warp >> 2;      // 0..3
    const int warp_n = warp & 3;       // 0..3
    const int bm = blockIdx.y * 128, bn = blockIdx.x * 128;
    const int KC = K >> 5;

    float accg[2][4][4], accu[2][4][4];
#pragma unroll
    for (int i = 0; i < 2; i++)
#pragma unroll
        for (int j = 0; j < 4; j++)
#pragma unroll
            for (int e = 0; e < 4; e++) { accg[i][j][e] = 0.f; accu[i][j][e] = 0.f; }

    auto load_stage = [&](int st, int k0) {
        int r = tid >> 2, c = tid & 3;
        uint32_t sa0 = sb + st * D_STAGE + r * 80 + c * 16;
#pragma unroll
        for (int t = 0; t < 6; t++) {
            const bf16* src = (t == 0) ? Ah : (t == 1) ? Al : (t == 2) ? B1h :
                              (t == 3) ? B1l : (t == 4) ? B2h : B2l;
            int row0 = (t < 2) ? bm : bn;
            const bf16* ga = src + (size_t)(row0 + r) * K + k0 + c * 8;
            asm volatile("cp.async.cg.shared.global [%0], [%1], 16;"
                         :: "r"(sa0 + t * TILE_B), "l"(ga));
        }
    };

    load_stage(0, 0);
    asm volatile("cp.async.commit_group;" ::: "memory");
    load_stage(1, 32);
    asm volatile("cp.async.commit_group;" ::: "memory");

    int st_c = 0, st_l = 2;
    for (int kc = 0; kc < KC; kc++) {
        asm volatile("cp.async.wait_group 1;" ::: "memory");
        __syncthreads();
        if (kc + 2 < KC) load_stage(st_l, (kc + 2) * 32);
        asm volatile("cp.async.commit_group;" ::: "memory");

        const uint32_t stage = sb + st_c * D_STAGE;
#pragma unroll
        for (int kk = 0; kk < 32; kk += 16) {
            uint32_t ah[2][4], al[2][4];
#pragma unroll
            for (int fm = 0; fm < 2; fm++) {
                int row = warp_m * 32 + fm * 16 + (lane & 15);
                int kw = kk + (lane >> 4) * 8;
                uint32_t a_addr = stage + row * 80 + kw * 2;
                LDSM_X4(ah[fm], a_addr);
                LDSM_X4(al[fm], a_addr + TILE_B);
            }
            int brow = warp_n * 32 + (lane & 15);
            int bkw = kk + (lane >> 4) * 8;
            {
                uint32_t bh[4][2], bl[4][2];
#pragma unroll
                for (int fp = 0; fp < 2; fp++) {
                    uint32_t b_addr = stage + 2 * TILE_B + (brow + fp * 16) * 80 + bkw * 2;
                    uint32_t th[4], tl[4];
                    LDSM_X4(th, b_addr);
                    LDSM_X4(tl, b_addr + TILE_B);
                    bh[2 * fp][0] = th[0]; bh[2 * fp + 1][0] = th[1];
                    bh[2 * fp][1] = th[2]; bh[2 * fp + 1][1] = th[3];
                    bl[2 * fp][0] = tl[0]; bl[2 * fp + 1][0] = tl[1];
                    bl[2 * fp][1] = tl[2]; bl[2 * fp + 1][1] = tl[3];
                }
#pragma unroll
                for (int fm = 0; fm < 2; fm++)
#pragma unroll
                    for (int fn = 0; fn < 4; fn++) {
                        MMA16816(accg[fm][fn], ah[fm], bh[fn]);
                        MMA16816(accg[fm][fn], ah[fm], bl[fn]);
                        MMA16816(accg[fm][fn], al[fm], bh[fn]);
                    }
            }
            {
                uint32_t bh[4][2], bl[4][2];
#pragma unroll
                for (int fp = 0; fp < 2; fp++) {
                    uint32_t b_addr = stage + 4 * TILE_B + (brow + fp * 16) * 80 + bkw * 2;
                    uint32_t th[4], tl[4];
                    LDSM_X4(th, b_addr);
                    LDSM_X4(tl, b_addr + TILE_B);
                    bh[2 * fp][0] = th[0]; bh[2 * fp + 1][0] = th[1];
                    bh[2 * fp][1] = th[2]; bh[2 * fp + 1][1] = th[3];
                    bl[2 * fp][0] = tl[0]; bl[2 * fp + 1][0] = tl[1];
                    bl[2 * fp][1] = tl[2]; bl[2 * fp + 1][1] = tl[3];
                }
#pragma unroll
                for (int fm = 0; fm < 2; fm++)
#pragma unroll
                    for (int fn = 0; fn < 4; fn++) {
                        MMA16816(accu[fm][fn], ah[fm], bh[fn]);
                        MMA16816(accu[fm][fn], ah[fm], bl[fn]);
                        MMA16816(accu[fm][fn], al[fm], bh[fn]);
                    }
            }
        }
        st_c++; if (st_c == D_NSTAGE) st_c = 0;
        st_l++; if (st_l == D_NSTAGE) st_l = 0;
    }

    // epilogue: h = silu(g)*u, split bf16 hi/lo
#pragma unroll
    for (int fm = 0; fm < 2; fm++)
#pragma unroll
        for (int fn = 0; fn < 4; fn++) {
            int row = bm + warp_m * 32 + fm * 16 + (lane >> 2);
            int col = bn + warp_n * 32 + fn * 8 + 2 * (lane & 3);
#pragma unroll
            for (int h = 0; h < 2; h++) {
                int r = row + h * 8;
                size_t off = (size_t)r * ldo + col;
                float gx = accg[fm][fn][2 * h], gy = accg[fm][fn][2 * h + 1];
                float ux = accu[fm][fn][2 * h], uy = accu[fm][fn][2 * h + 1];
                float h0 = gx / (1.f + expf(-gx)) * ux;
                float h1 = gy / (1.f + expf(-gy)) * uy;
                bf16 h0h = __float2bfloat16_rn(h0);
                bf16 h1h = __float2bfloat16_rn(h1);
                bf16 h0l = __float2bfloat16_rn(h0 - __bfloat162float(h0h));
                bf16 h1l = __float2bfloat16_rn(h1 - __bfloat162float(h1h));
                *(__nv_bfloat162*)(Hh + off) = __halves2bfloat162(h0h, h1h);
                *(__nv_bfloat162*)(Hl + off) = __halves2bfloat162(h0l, h1l);
            }
        }
}

// ================= fp32 -> bf16 hi/lo split =================
__global__ void split_kernel(const float* __restrict__ s, bf16* __restrict__ hi,
                             bf16* __restrict__ lo, int n4)
{
    int i = blockIdx.x * blockDim.x + threadIdx.x;
    if (i >= n4) return;
    float4 v = ((const float4*)s)[i];
    float vv[4] = {v.x, v.y, v.z, v.w};
    bf16 h[4], l[4];
#pragma unroll
    for (int j = 0; j < 4; j++) {
        h[j] = __float2bfloat16_rn(vv[j]);
        l[j] = __float2bfloat16_rn(vv[j] - __bfloat162float(h[j]));
    }
    ((__nv_bfloat162*)hi)[2 * i]     = __halves2bfloat162(h[0], h[1]);
    ((__nv_bfloat162*)hi)[2 * i + 1] = __halves2bfloat162(h[2], h[3]);
    ((__nv_bfloat162*)lo)[2 * i]     = __halves2bfloat162(l[0], l[1]);
    ((__nv_bfloat162*)lo)[2 * i + 1] = __halves2bfloat162(l[2], l[3]);
}

// ================= batch stats =================
__global__ void col_stats()
{
    const int c = blockIdx.x;
    const float* r = (c < NS) ? g_rx : g_ry;
    const int col = c & (NS - 1);
    float s = 0.f, s2 = 0.f;
    for (int i = threadIdx.x; i < NTOK; i += 256) {
        float v = r[i * NS + col];
        s += v; s2 += v * v;
    }
    __shared__ float sh[64];
#pragma unroll
    for (int o = 16; o; o >>= 1) {
        s  += __shfl_down_sync(0xffffffffu, s,  o);
        s2 += __shfl_down_sync(0xffffffffu, s2, o);
    }
    const int w = threadIdx.x >> 5;
    if ((threadIdx.x & 31) == 0) { sh[w] = s; sh[32 + w] = s2; }
    __syncthreads();
    if (threadIdx.x == 0) {
        float S = 0.f, S2 = 0.f;
        for (int i = 0; i < 8; i++) { S += sh[i]; S2 += sh[32 + i]; }
        float m = S / (float)NTOK;
        float var = S2 / (float)NTOK - m * m;
        g_mean[c] = m;
        g_rstd[c] = rsqrtf(var + BN_EPS);
    }
}

// ================= bn + log_softmax =================
__global__ void bn_logsoftmax()
{
    const int n = blockIdx.x;
    const int c = threadIdx.x;
    __shared__ float sh[4];
#pragma unroll
    for (int r = 0; r < 2; r++) {
        float* buf = r ? g_ry : g_rx;
        float z = (buf[n * NS + c] - g_mean[r * NS + c]) * g_rstd[r * NS + c];
        float v = z;
#pragma unroll
        for (int o = 16; o; o >>= 1) v = fmaxf(v, __shfl_xor_sync(0xffffffffu, v, o));
        if ((c & 31) == 0) sh[c >> 5] = v;
        __syncthreads();
        float m = fmaxf(fmaxf(sh[0], sh[1]), fmaxf(sh[2], sh[3]));
        __syncthreads();
        float e = expf(z - m), sv = e;
#pragma unroll
        for (int o = 16; o; o >>= 1) sv += __shfl_xor_sync(0xffffffffu, sv, o);
        if ((c & 31) == 0) sh[c >> 5] = sv;
        __syncthreads();
        float tot = sh[0] + sh[1] + sh[2] + sh[3];
        buf[n * NS + c] = z - (m + logf(tot));
        __syncthreads();
    }
}

// ================= product-key top-k =================
__global__ void topk_kernel()
{
    const int n = blockIdx.x;
    const int lane = threadIdx.x;
    __shared__ float sx[16], sy[16];
    __shared__ int sxi[16], syi[16];
    const float* rowx = g_rx + n * NS;
    const float* rowy = g_ry + n * NS;
    float vx[4], vy[4];
#pragma unroll
    for (int j = 0; j < 4; j++) { vx[j] = rowx[lane * 4 + j]; vy[j] = rowy[lane * 4 + j]; }

    for (int t = 0; t < 16; t++) {
        float bv = -INFINITY; int bj = 0;
#pragma unroll
        for (int j = 0; j < 4; j++) if (vx[j] > bv) { bv = vx[j]; bj = j; }
        int bl = lane;
#pragma unroll
        for (int o = 16; o; o >>= 1) {
            float ov = __shfl_down_sync(0xffffffffu, bv, o);
            int ol = __shfl_down_sync(0xffffffffu, bl, o);
            int oj = __shfl_down_sync(0xffffffffu, bj, o);
            if (ov > bv) { bv = ov; bl = ol; bj = oj; }
        }
        bv = __shfl_sync(0xffffffffu, bv, 0);
        bl = __shfl_sync(0xffffffffu, bl, 0);
        bj = __shfl_sync(0xffffffffu, bj, 0);
        if (lane == bl) {
#pragma unroll
            for (int j = 0; j < 4; j++) if (j == bj) vx[j] = -INFINITY;
        }
        if (lane == 0) { sx[t] = bv; sxi[t] = bl * 4 + bj; }
    }
    for (int t = 0; t < 16; t++) {
        float bv = -INFINITY; int bj = 0;
#pragma unroll
        for (int j = 0; j < 4; j++) if (vy[j] > bv) { bv = vy[j]; bj = j; }
        int bl = lane;
#pragma unroll
        for (int o = 16; o; o >>= 1) {
            float ov = __shfl_down_sync(0xffffffffu, bv, o);
            int ol = __shfl_down_sync(0xffffffffu, bl, o);
            int oj = __shfl_down_sync(0xffffffffu, bj, o);
            if (ov > bv) { bv = ov; bl = ol; bj = oj; }
        }
        bv = __shfl_sync(0xffffffffu, bv, 0);
        bl = __shfl_sync(0xffffffffu, bl, 0);
        bj = __shfl_sync(0xffffffffu, bj, 0);
        if (lane == bl) {
#pragma unroll
            for (int j = 0; j < 4; j++) if (j == bj) vy[j] = -INFINITY;
        }
        if (lane == 0) { sy[t] = bv; syi[t] = bl * 4 + bj; }
    }
    __syncwarp();

    float cv[8];
#pragma unroll
    for (int j = 0; j < 8; j++) {
        int p = lane * 8 + j;
        cv[j] = sx[p >> 4] + sy[p & 15];
    }
    for (int t = 0; t < 16; t++) {
        float bv = -INFINITY; int bj = 0;
#pragma unroll
        for (int j = 0; j < 8; j++) if (cv[j] > bv) { bv = cv[j]; bj = j; }
        int bl = lane;
#pragma unroll
        for (int o = 16; o; o >>= 1) {
            float ov = __shfl_down_sync(0xffffffffu, bv, o);
            int ol = __shfl_down_sync(0xffffffffu, bl, o);
            int oj = __shfl_down_sync(0xffffffffu, bj, o);
            if (ov > bv) { bv = ov; bl = ol; bj = oj; }
        }
        bv = __shfl_sync(0xffffffffu, bv, 0);
        bl = __shfl_sync(0xffffffffu, bl, 0);
        bj = __shfl_sync(0xffffffffu, bj, 0);
        if (lane == bl) {
#pragma unroll
            for (int j = 0; j < 8; j++) if (j == bj) cv[j] = -INFINITY;
        }
        if (lane == 0) {
            int p = bl * 8 + bj;
            g_idx[n * TOPK + t] = sxi[p >> 4] * NS + syi[p & 15];
            g_wk[n * TOPK + t] = expf(bv);
        }
    }
}

// ================= expert gather (writes g_eout) =================
__global__ __launch_bounds__(256) void expert_kernel(
    const float* __restrict__ x,
    const float* __restrict__ up_e,
    const float* __restrict__ down_e)
{
    const int n = blockIdx.x;
    __shared__ float sx[HDIM];
    __shared__ float sew[TOPK];
    const int tid = threadIdx.x;
    for (int i = tid; i < HDIM; i += 256) sx[i] = x[(size_t)n * HDIM + i];
    __syncthreads();
    const int warp = tid >> 5, lane = tid & 31;
#pragma unroll
    for (int k = warp; k < TOPK; k += 8) {
        int e = g_idx[n * TOPK + k];
        const float* ue = up_e + (size_t)e * HDIM;
        float d = 0.f;
#pragma unroll
        for (int i = lane * 4; i < HDIM; i += 128) {
            float4 u = *(const float4*)(ue + i);
            d += u.x * sx[i] + u.y * sx[i + 1] + u.z * sx[i + 2] + u.w * sx[i + 3];
        }
#pragma unroll
        for (int o = 16; o; o >>= 1) d += __shfl_down_sync(0xffffffffu, d, o);
        if (lane == 0) {
            float s = d / (1.f + expf(-d));
            sew[k] = s * g_wk[n * TOPK + k];
        }
    }
    __syncthreads();
    float acc[4] = {0.f, 0.f, 0.f, 0.f};
#pragma unroll
    for (int k = 0; k < TOPK; k++) {
        int e = g_idx[n * TOPK + k];
        float wk = sew[k];
        const float* de = down_e + (size_t)e * HDIM;
#pragma unroll
        for (int j = 0; j < 4; j++) acc[j] += wk * de[tid + j * 256];
    }
#pragma unroll
    for (int j = 0; j < 4; j++)
        g_eout[(size_t)n * HDIM + tid + j * 256] = acc[j];
}

// ================= launch =================
extern "C" void kernel_launch(void* const* d_in, const int* in_sizes, int n_in,
                              void* d_out, int out_size)
{
    const float* x      = (const float*)d_in[0];
    const float* gate_w = (const float*)d_in[1];
    const float* up_w   = (const float*)d_in[2];
    const float* down_w = (const float*)d_in[3];
    const float* rxw    = (const float*)d_in[4];
    const float* ryw    = (const float*)d_in[5];
    const float* up_e   = (const float*)d_in[6];
    const float* down_e = (const float*)d_in[7];
    float* out = (float*)d_out;

    float *rx, *ry, *eo;
    cudaGetSymbolAddress((void**)&rx, g_rx);
    cudaGetSymbolAddress((void**)&ry, g_ry);
    cudaGetSymbolAddress((void**)&eo, g_eout);
    bf16 *xh, *xl, *gwh, *gwl, *uwh, *uwl, *dwh, *dwl, *hh, *hl;
    bf16 *rwxh, *rwxl, *rwyh, *rwyl;
    cudaGetSymbolAddress((void**)&xh, g_xh);   cudaGetSymbolAddress((void**)&xl, g_xl);
    cudaGetSymbolAddress((void**)&gwh, g_gwh); cudaGetSymbolAddress((void**)&gwl, g_gwl);
    cudaGetSymbolAddress((void**)&uwh, g_uwh); cudaGetSymbolAddress((void**)&uwl, g_uwl);
    cudaGetSymbolAddress((void**)&dwh, g_dwh); cudaGetSymbolAddress((void**)&dwl, g_dwl);
    cudaGetSymbolAddress((void**)&rwxh, g_rwxh); cudaGetSymbolAddress((void**)&rwxl, g_rwxl);
    cudaGetSymbolAddress((void**)&rwyh, g_rwyh); cudaGetSymbolAddress((void**)&rwyl, g_rwyl);
    cudaGetSymbolAddress((void**)&hh, g_hh);   cudaGetSymbolAddress((void**)&hl, g_hl);

    const int SMEM_S = 2 * S2_STAGE;          // 81920 -> 2 CTAs/SM
    const int SMEM_D = D_NSTAGE * D_STAGE;    // 184320 -> 1 CTA/SM
    static cudaStream_t s2 = nullptr;
    static cudaEvent_t ev1 = nullptr, ev2 = nullptr;
    if (!s2) {
        cudaFuncSetAttribute(mma_gemm_s<0>, cudaFuncAttributeMaxDynamicSharedMemorySize, SMEM_S);
        cudaFuncSetAttribute(mma_gemm_s<2>, cudaFuncAttributeMaxDynamicSharedMemorySize, SMEM_S);
        cudaFuncSetAttribute(mma_gemm_dual, cudaFuncAttributeMaxDynamicSharedMemorySize, SMEM_D);
        cudaStreamCreateWithFlags(&s2, cudaStreamNonBlocking);
        cudaEventCreateWithFlags(&ev1, cudaEventDisableTiming);
        cudaEventCreateWithFlags(&ev2, cudaEventDisableTiming);
    }

    // x split on main stream (needed by both branches)
    int n4 = NTOK * HDIM / 4;
    split_kernel<<<(n4 + 255) / 256, 256>>>(x, xh, xl, n4);
    cudaEventRecord(ev1, 0);
    cudaStreamWaitEvent(s2, ev1, 0);

    // ---- side stream: down_w split + router chain + expert gather ----
    int w4 = IDIM * HDIM / 4;
    split_kernel<<<(w4 + 255) / 256, 256, 0, s2>>>(down_w, dwh, dwl, w4);
    int r4 = NS * HDIM / 4;
    split_kernel<<<(r4 + 255) / 256, 256, 0, s2>>>(rxw, rwxh, rwxl, r4);
    split_kernel<<<(r4 + 255) / 256, 256, 0, s2>>>(ryw, rwyh, rwyl, r4);
    mma_gemm_s<0><<<dim3(1, NTOK / 128), 256, SMEM_S, s2>>>(
        xh, xl, rwxh, rwxl, nullptr, rx, HDIM, NS);
    mma_gemm_s<0><<<dim3(1, NTOK / 128), 256, SMEM_S, s2>>>(
        xh, xl, rwyh, rwyl, nullptr, ry, HDIM, NS);
    col_stats<<<2 * NS, 256, 0, s2>>>();
    bn_logsoftmax<<<NTOK, NS, 0, s2>>>();
    topk_kernel<<<NTOK, 32, 0, s2>>>();
    expert_kernel<<<NTOK, 256, 0, s2>>>(x, up_e, down_e);
    cudaEventRecord(ev2, s2);

    // ---- main stream: dense MLP ----
    split_kernel<<<(w4 + 255) / 256, 256>>>(gate_w, gwh, gwl, w4);
    split_kernel<<<(w4 + 255) / 256, 256>>>(up_w,   uwh, uwl, w4);

    // fused gate+up -> h (bf16 hi/lo)
    mma_gemm_dual<<<dim3(IDIM / 128, NTOK / 128), 512, SMEM_D>>>(
        xh, xl, gwh, gwl, uwh, uwl, hh, hl, HDIM, IDIM);

    // join expert branch, then down GEMM with fused expert add
    cudaStreamWaitEvent(0, ev2, 0);
    mma_gemm_s<2><<<dim3(HDIM / 128, NTOK / 128), 256, SMEM_S>>>(
        hh, hl, dwh, dwl, eo, out, IDIM, HDIM);
}

// round 11
// speedup vs baseline: 1.0368x; 1.0368x over previous
#include <cuda_runtime.h>
#include <cuda_bf16.h>
#include <math.h>
#include <stdint.h>

#define NTOK 4096   // B*S
#define HDIM 1024
#define IDIM 4096
#define NS   128
#define TOPK 16
#define BN_EPS 1e-5f

typedef __nv_bfloat16 bf16;

// ================= scratch (static device allocations) =================
__device__ float g_rx[NTOK * NS];
__device__ float g_ry[NTOK * NS];
__device__ float g_mean[2 * NS];
__device__ float g_rstd[2 * NS];
__device__ int   g_idx[NTOK * TOPK];
__device__ float g_wk[NTOK * TOPK];
__device__ float g_eout[(size_t)NTOK * HDIM];
// bf16 split operands
__device__ bf16 g_xh[NTOK * HDIM],  g_xl[NTOK * HDIM];
__device__ bf16 g_gwh[IDIM * HDIM], g_gwl[IDIM * HDIM];
__device__ bf16 g_uwh[IDIM * HDIM], g_uwl[IDIM * HDIM];
__device__ bf16 g_dwh[HDIM * IDIM], g_dwl[HDIM * IDIM];
__device__ bf16 g_rwxh[NS * HDIM], g_rwxl[NS * HDIM];
__device__ bf16 g_rwyh[NS * HDIM], g_rwyl[NS * HDIM];
__device__ bf16 g_hh[(size_t)NTOK * IDIM], g_hl[(size_t)NTOK * IDIM];

// ================= helpers =================
__device__ __forceinline__ uint32_t smem_to_u32(const void* p) {
    uint32_t a;
    asm("{ .reg .u64 t; cvta.to.shared.u64 t, %1; cvt.u32.u64 %0, t; }" : "=r"(a) : "l"(p));
    return a;
}

#define MMA16816(c, a, b) \
    asm volatile("mma.sync.aligned.m16n8k16.row.col.f32.bf16.bf16.f32 " \
        "{%0,%1,%2,%3}, {%4,%5,%6,%7}, {%8,%9}, {%0,%1,%2,%3};" \
        : "+f"((c)[0]), "+f"((c)[1]), "+f"((c)[2]), "+f"((c)[3]) \
        : "r"((a)[0]), "r"((a)[1]), "r"((a)[2]), "r"((a)[3]), "r"((b)[0]), "r"((b)[1]))

#define LDSM_X4(r, addr) \
    asm volatile("ldmatrix.sync.aligned.m8n8.x4.shared.b16 {%0,%1,%2,%3}, [%4];" \
        : "=r"((r)[0]), "=r"((r)[1]), "=r"((r)[2]), "=r"((r)[3]) : "r"(addr))

#define TILE_B 10240   // 128 rows * 80B (32 bf16 + 8B pad), conflict-free for ldmatrix

// ================= unified bf16x3 tensor-core GEMM =================
// C[M,N(128)] = (Ah+Al)[M,K] * (B1h+B1l)[N,K]^T (+ second B if DUAL), fp32 accum.
// 512 threads = 16 warps (4x4 of 32x32 warp tiles), 128x128 CTA tile, BK=32,
// NST-stage cp.async pipeline, one barrier per mainloop iteration.
// MODE 0: Cout = acc.  MODE 2: Cout = acc + E.  MODE 1 (DUAL): h=silu(g)*u -> bf16 hi/lo.

template<bool DUAL, int MODE, int NST>
__global__ __launch_bounds__(512, 1) void mma_gemm_u(
    const bf16* __restrict__ Ah, const bf16* __restrict__ Al,
    const bf16* __restrict__ B1h, const bf16* __restrict__ B1l,
    const bf16* __restrict__ B2h, const bf16* __restrict__ B2l,
    const float* __restrict__ E, float* __restrict__ Cout,
    bf16* __restrict__ Hh, bf16* __restrict__ Hl, int K, int ldo)
{
    constexpr int NTILE = DUAL ? 6 : 4;
    constexpr int STAGE = NTILE * TILE_B;
    extern __shared__ __align__(128) char smem[];
    const uint32_t sb = smem_to_u32(smem);
    const int tid = threadIdx.x;
    const int lane = tid & 31;
    const int warp = tid >> 5;
    const int warp_m = warp >> 2;      // 0..3
    const int warp_n = warp & 3;       // 0..3
    const int bm = blockIdx.y * 128, bn = blockIdx.x * 128;
    const int KC = K >> 5;

    float accg[2][4][4];
    float accu[2][4][4];
#pragma unroll
    for (int i = 0; i < 2; i++)
#pragma unroll
        for (int j = 0; j < 4; j++)
#pragma unroll
            for (int e = 0; e < 4; e++) { accg[i][j][e] = 0.f; if (DUAL) accu[i][j][e] = 0.f; }

    // 512 threads x 16B = 8KB = exactly one 128x32 bf16 tile per pass
    auto load_stage = [&](int st, int k0) {
        int r = tid >> 2, c = tid & 3;
        uint32_t sa0 = sb + st * STAGE + r * 80 + c * 16;
#pragma unroll
        for (int t = 0; t < NTILE; t++) {
            const bf16* src = (t == 0) ? Ah : (t == 1) ? Al : (t == 2) ? B1h :
                              (t == 3) ? B1l : (t == 4) ? B2h : B2l;
            int row0 = (t < 2) ? bm : bn;
            const bf16* ga = src + (size_t)(row0 + r) * K + k0 + c * 8;
            asm volatile("cp.async.cg.shared.global [%0], [%1], 16;"
                         :: "r"(sa0 + t * TILE_B), "l"(ga));
        }
    };

#pragma unroll
    for (int p = 0; p < NST - 1; p++) {
        load_stage(p, p * 32);
        asm volatile("cp.async.commit_group;" ::: "memory");
    }

    int st_c = 0, st_l = NST - 1;
    for (int kc = 0; kc < KC; kc++) {
        asm volatile("cp.async.wait_group %0;" :: "n"(NST - 2) : "memory");
        __syncthreads();
        // issue next loads (overwrites stage computed at kc-1; barrier above protects it)
        if (kc + NST - 1 < KC) load_stage(st_l, (kc + NST - 1) * 32);
        asm volatile("cp.async.commit_group;" ::: "memory");

        const uint32_t stage = sb + st_c * STAGE;
#pragma unroll
        for (int kk = 0; kk < 32; kk += 16) {
            uint32_t ah[2][4], al[2][4];
#pragma unroll
            for (int fm = 0; fm < 2; fm++) {
                int row = warp_m * 32 + fm * 16 + (lane & 15);
                int kw = kk + (lane >> 4) * 8;
                uint32_t a_addr = stage + row * 80 + kw * 2;
                LDSM_X4(ah[fm], a_addr);
                LDSM_X4(al[fm], a_addr + TILE_B);
            }
            int brow = warp_n * 32 + (lane & 15);
            int bkw = kk + (lane >> 4) * 8;
            // B1
            {
                uint32_t bh[4][2], bl[4][2];
#pragma unroll
                for (int fp = 0; fp < 2; fp++) {
                    uint32_t b_addr = stage + 2 * TILE_B + (brow + fp * 16) * 80 + bkw * 2;
                    uint32_t th[4], tl[4];
                    LDSM_X4(th, b_addr);
                    LDSM_X4(tl, b_addr + TILE_B);
                    bh[2 * fp][0] = th[0]; bh[2 * fp + 1][0] = th[1];
                    bh[2 * fp][1] = th[2]; bh[2 * fp + 1][1] = th[3];
                    bl[2 * fp][0] = tl[0]; bl[2 * fp + 1][0] = tl[1];
                    bl[2 * fp][1] = tl[2]; bl[2 * fp + 1][1] = tl[3];
                }
#pragma unroll
                for (int fm = 0; fm < 2; fm++)
#pragma unroll
                    for (int fn = 0; fn < 4; fn++) {
                        MMA16816(accg[fm][fn], ah[fm], bh[fn]);
                        MMA16816(accg[fm][fn], ah[fm], bl[fn]);
                        MMA16816(accg[fm][fn], al[fm], bh[fn]);
                    }
            }
            // B2 (dual only)
            if (DUAL) {
                uint32_t bh[4][2], bl[4][2];
#pragma unroll
                for (int fp = 0; fp < 2; fp++) {
                    uint32_t b_addr = stage + 4 * TILE_B + (brow + fp * 16) * 80 + bkw * 2;
                    uint32_t th[4], tl[4];
                    LDSM_X4(th, b_addr);
                    LDSM_X4(tl, b_addr + TILE_B);
                    bh[2 * fp][0] = th[0]; bh[2 * fp + 1][0] = th[1];
                    bh[2 * fp][1] = th[2]; bh[2 * fp + 1][1] = th[3];
                    bl[2 * fp][0] = tl[0]; bl[2 * fp + 1][0] = tl[1];
                    bl[2 * fp][1] = tl[2]; bl[2 * fp + 1][1] = tl[3];
                }
#pragma unroll
                for (int fm = 0; fm < 2; fm++)
#pragma unroll
                    for (int fn = 0; fn < 4; fn++) {
                        MMA16816(accu[fm][fn], ah[fm], bh[fn]);
                        MMA16816(accu[fm][fn], ah[fm], bl[fn]);
                        MMA16816(accu[fm][fn], al[fm], bh[fn]);
                    }
            }
        }
        st_c++; if (st_c == NST) st_c = 0;
        st_l++; if (st_l == NST) st_l = 0;
    }

    // ---------------- epilogue ----------------
#pragma unroll
    for (int fm = 0; fm < 2; fm++)
#pragma unroll
        for (int fn = 0; fn < 4; fn++) {
            int row = bm + warp_m * 32 + fm * 16 + (lane >> 2);
            int col = bn + warp_n * 32 + fn * 8 + 2 * (lane & 3);
#pragma unroll
            for (int h = 0; h < 2; h++) {
                int r = row + h * 8;
                size_t off = (size_t)r * ldo + col;
                float d0 = accg[fm][fn][2 * h], d1 = accg[fm][fn][2 * h + 1];
                if (MODE == 1) {
                    float ux = accu[fm][fn][2 * h], uy = accu[fm][fn][2 * h + 1];
                    float h0 = d0 / (1.f + expf(-d0)) * ux;
                    float h1 = d1 / (1.f + expf(-d1)) * uy;
                    bf16 h0h = __float2bfloat16_rn(h0);
                    bf16 h1h = __float2bfloat16_rn(h1);
                    bf16 h0l = __float2bfloat16_rn(h0 - __bfloat162float(h0h));
                    bf16 h1l = __float2bfloat16_rn(h1 - __bfloat162float(h1h));
                    *(__nv_bfloat162*)(Hh + off) = __halves2bfloat162(h0h, h1h);
                    *(__nv_bfloat162*)(Hl + off) = __halves2bfloat162(h0l, h1l);
                } else {
                    if (MODE == 2) {
                        float2 e = *(const float2*)(E + off);
                        d0 += e.x; d1 += e.y;
                    }
                    *(float2*)(Cout + off) = make_float2(d0, d1);
                }
            }
        }
}

// ================= fp32 -> bf16 hi/lo split =================
__global__ void split_kernel(const float* __restrict__ s, bf16* __restrict__ hi,
                             bf16* __restrict__ lo, int n4)
{
    int i = blockIdx.x * blockDim.x + threadIdx.x;
    if (i >= n4) return;
    float4 v = ((const float4*)s)[i];
    float vv[4] = {v.x, v.y, v.z, v.w};
    bf16 h[4], l[4];
#pragma unroll
    for (int j = 0; j < 4; j++) {
        h[j] = __float2bfloat16_rn(vv[j]);
        l[j] = __float2bfloat16_rn(vv[j] - __bfloat162float(h[j]));
    }
    ((__nv_bfloat162*)hi)[2 * i]     = __halves2bfloat162(h[0], h[1]);
    ((__nv_bfloat162*)hi)[2 * i + 1] = __halves2bfloat162(h[2], h[3]);
    ((__nv_bfloat162*)lo)[2 * i]     = __halves2bfloat162(l[0], l[1]);
    ((__nv_bfloat162*)lo)[2 * i + 1] = __halves2bfloat162(l[2], l[3]);
}

// ================= batch stats =================
__global__ void col_stats()
{
    const int c = blockIdx.x;
    const float* r = (c < NS) ? g_rx : g_ry;
    const int col = c & (NS - 1);
    float s = 0.f, s2 = 0.f;
    for (int i = threadIdx.x; i < NTOK; i += 256) {
        float v = r[i * NS + col];
        s += v; s2 += v * v;
    }
    __shared__ float sh[64];
#pragma unroll
    for (int o = 16; o; o >>= 1) {
        s  += __shfl_down_sync(0xffffffffu, s,  o);
        s2 += __shfl_down_sync(0xffffffffu, s2, o);
    }
    const int w = threadIdx.x >> 5;
    if ((threadIdx.x & 31) == 0) { sh[w] = s; sh[32 + w] = s2; }
    __syncthreads();
    if (threadIdx.x == 0) {
        float S = 0.f, S2 = 0.f;
        for (int i = 0; i < 8; i++) { S += sh[i]; S2 += sh[32 + i]; }
        float m = S / (float)NTOK;
        float var = S2 / (float)NTOK - m * m;
        g_mean[c] = m;
        g_rstd[c] = rsqrtf(var + BN_EPS);
    }
}

// ================= bn + log_softmax =================
__global__ void bn_logsoftmax()
{
    const int n = blockIdx.x;
    const int c = threadIdx.x;
    __shared__ float sh[4];
#pragma unroll
    for (int r = 0; r < 2; r++) {
        float* buf = r ? g_ry : g_rx;
        float z = (buf[n * NS + c] - g_mean[r * NS + c]) * g_rstd[r * NS + c];
        float v = z;
#pragma unroll
        for (int o = 16; o; o >>= 1) v = fmaxf(v, __shfl_xor_sync(0xffffffffu, v, o));
        if ((c & 31) == 0) sh[c >> 5] = v;
        __syncthreads();
        float m = fmaxf(fmaxf(sh[0], sh[1]), fmaxf(sh[2], sh[3]));
        __syncthreads();
        float e = expf(z - m), sv = e;
#pragma unroll
        for (int o = 16; o; o >>= 1) sv += __shfl_xor_sync(0xffffffffu, sv, o);
        if ((c & 31) == 0) sh[c >> 5] = sv;
        __syncthreads();
        float tot = sh[0] + sh[1] + sh[2] + sh[3];
        buf[n * NS + c] = z - (m + logf(tot));
        __syncthreads();
    }
}

// ================= product-key top-k =================
__global__ void topk_kernel()
{
    const int n = blockIdx.x;
    const int lane = threadIdx.x;
    __shared__ float sx[16], sy[16];
    __shared__ int sxi[16], syi[16];
    const float* rowx = g_rx + n * NS;
    const float* rowy = g_ry + n * NS;
    float vx[4], vy[4];
#pragma unroll
    for (int j = 0; j < 4; j++) { vx[j] = rowx[lane * 4 + j]; vy[j] = rowy[lane * 4 + j]; }

    for (int t = 0; t < 16; t++) {
        float bv = -INFINITY; int bj = 0;
#pragma unroll
        for (int j = 0; j < 4; j++) if (vx[j] > bv) { bv = vx[j]; bj = j; }
        int bl = lane;
#pragma unroll
        for (int o = 16; o; o >>= 1) {
            float ov = __shfl_down_sync(0xffffffffu, bv, o);
            int ol = __shfl_down_sync(0xffffffffu, bl, o);
            int oj = __shfl_down_sync(0xffffffffu, bj, o);
            if (ov > bv) { bv = ov; bl = ol; bj = oj; }
        }
        bv = __shfl_sync(0xffffffffu, bv, 0);
        bl = __shfl_sync(0xffffffffu, bl, 0);
        bj = __shfl_sync(0xffffffffu, bj, 0);
        if (lane == bl) {
#pragma unroll
            for (int j = 0; j < 4; j++) if (j == bj) vx[j] = -INFINITY;
        }
        if (lane == 0) { sx[t] = bv; sxi[t] = bl * 4 + bj; }
    }
    for (int t = 0; t < 16; t++) {
        float bv = -INFINITY; int bj = 0;
#pragma unroll
        for (int j = 0; j < 4; j++) if (vy[j] > bv) { bv = vy[j]; bj = j; }
        int bl = lane;
#pragma unroll
        for (int o = 16; o; o >>= 1) {
            float ov = __shfl_down_sync(0xffffffffu, bv, o);
            int ol = __shfl_down_sync(0xffffffffu, bl, o);
            int oj = __shfl_down_sync(0xffffffffu, bj, o);
            if (ov > bv) { bv = ov; bl = ol; bj = oj; }
        }
        bv = __shfl_sync(0xffffffffu, bv, 0);
        bl = __shfl_sync(0xffffffffu, bl, 0);
        bj = __shfl_sync(0xffffffffu, bj, 0);
        if (lane == bl) {
#pragma unroll
            for (int j = 0; j < 4; j++) if (j == bj) vy[j] = -INFINITY;
        }
        if (lane == 0) { sy[t] = bv; syi[t] = bl * 4 + bj; }
    }
    __syncwarp();

    float cv[8];
#pragma unroll
    for (int j = 0; j < 8; j++) {
        int p = lane * 8 + j;
        cv[j] = sx[p >> 4] + sy[p & 15];
    }
    for (int t = 0; t < 16; t++) {
        float bv = -INFINITY; int bj = 0;
#pragma unroll
        for (int j = 0; j < 8; j++) if (cv[j] > bv) { bv = cv[j]; bj = j; }
        int bl = lane;
#pragma unroll
        for (int o = 16; o; o >>= 1) {
            float ov = __shfl_down_sync(0xffffffffu, bv, o);
            int ol = __shfl_down_sync(0xffffffffu, bl, o);
            int oj = __shfl_down_sync(0xffffffffu, bj, o);
            if (ov > bv) { bv = ov; bl = ol; bj = oj; }
        }
        bv = __shfl_sync(0xffffffffu, bv, 0);
        bl = __shfl_sync(0xffffffffu, bl, 0);
        bj = __shfl_sync(0xffffffffu, bj, 0);
        if (lane == bl) {
#pragma unroll
            for (int j = 0; j < 8; j++) if (j == bj) cv[j] = -INFINITY;
        }
        if (lane == 0) {
            int p = bl * 8 + bj;
            g_idx[n * TOPK + t] = sxi[p >> 4] * NS + syi[p & 15];
            g_wk[n * TOPK + t] = expf(bv);
        }
    }
}

// ================= expert gather (writes g_eout) =================
__global__ __launch_bounds__(256) void expert_kernel(
    const float* __restrict__ x,
    const float* __restrict__ up_e,
    const float* __restrict__ down_e)
{
    const int n = blockIdx.x;
    __shared__ float sx[HDIM];
    __shared__ float sew[TOPK];
    const int tid = threadIdx.x;
    for (int i = tid; i < HDIM; i += 256) sx[i] = x[(size_t)n * HDIM + i];
    __syncthreads();
    const int warp = tid >> 5, lane = tid & 31;
#pragma unroll
    for (int k = warp; k < TOPK; k += 8) {
        int e = g_idx[n * TOPK + k];
        const float* ue = up_e + (size_t)e * HDIM;
        float d = 0.f;
#pragma unroll
        for (int i = lane * 4; i < HDIM; i += 128) {
            float4 u = *(const float4*)(ue + i);
            d += u.x * sx[i] + u.y * sx[i + 1] + u.z * sx[i + 2] + u.w * sx[i + 3];
        }
#pragma unroll
        for (int o = 16; o; o >>= 1) d += __shfl_down_sync(0xffffffffu, d, o);
        if (lane == 0) {
            float s = d / (1.f + expf(-d));
            sew[k] = s * g_wk[n * TOPK + k];
        }
    }
    __syncthreads();
    float acc[4] = {0.f, 0.f, 0.f, 0.f};
#pragma unroll
    for (int k = 0; k < TOPK; k++) {
        int e = g_idx[n * TOPK + k];
        float wk = sew[k];
        const float* de = down_e + (size_t)e * HDIM;
#pragma unroll
        for (int j = 0; j < 4; j++) acc[j] += wk * de[tid + j * 256];
    }
#pragma unroll
    for (int j = 0; j < 4; j++)
        g_eout[(size_t)n * HDIM + tid + j * 256] = acc[j];
}

// ================= launch =================
extern "C" void kernel_launch(void* const* d_in, const int* in_sizes, int n_in,
                              void* d_out, int out_size)
{
    const float* x      = (const float*)d_in[0];
    const float* gate_w = (const float*)d_in[1];
    const float* up_w   = (const float*)d_in[2];
    const float* down_w = (const float*)d_in[3];
    const float* rxw    = (const float*)d_in[4];
    const float* ryw    = (const float*)d_in[5];
    const float* up_e   = (const float*)d_in[6];
    const float* down_e = (const float*)d_in[7];
    float* out = (float*)d_out;

    float *rx, *ry, *eo;
    cudaGetSymbolAddress((void**)&rx, g_rx);
    cudaGetSymbolAddress((void**)&ry, g_ry);
    cudaGetSymbolAddress((void**)&eo, g_eout);
    bf16 *xh, *xl, *gwh, *gwl, *uwh, *uwl, *dwh, *dwl, *hh, *hl;
    bf16 *rwxh, *rwxl, *rwyh, *rwyl;
    cudaGetSymbolAddress((void**)&xh, g_xh);   cudaGetSymbolAddress((void**)&xl, g_xl);
    cudaGetSymbolAddress((void**)&gwh, g_gwh); cudaGetSymbolAddress((void**)&gwl, g_gwl);
    cudaGetSymbolAddress((void**)&uwh, g_uwh); cudaGetSymbolAddress((void**)&uwl, g_uwl);
    cudaGetSymbolAddress((void**)&dwh, g_dwh); cudaGetSymbolAddress((void**)&dwl, g_dwl);
    cudaGetSymbolAddress((void**)&rwxh, g_rwxh); cudaGetSymbolAddress((void**)&rwxl, g_rwxl);
    cudaGetSymbolAddress((void**)&rwyh, g_rwyh); cudaGetSymbolAddress((void**)&rwyl, g_rwyl);
    cudaGetSymbolAddress((void**)&hh, g_hh);   cudaGetSymbolAddress((void**)&hl, g_hl);

    const int SMEM_S = 4 * 4 * TILE_B;   // 4-stage single: 163840 -> 1 CTA/SM
    const int SMEM_D = 3 * 6 * TILE_B;   // 3-stage dual:   184320 -> 1 CTA/SM
    static cudaStream_t s2 = nullptr, s3 = nullptr;
    static cudaEvent_t ev0 = nullptr, ev1 = nullptr, ev2 = nullptr, ev3 = nullptr;
    if (!s2) {
        cudaFuncSetAttribute((const void*)mma_gemm_u<false, 0, 4>, cudaFuncAttributeMaxDynamicSharedMemorySize, SMEM_S);
        cudaFuncSetAttribute((const void*)mma_gemm_u<false, 2, 4>, cudaFuncAttributeMaxDynamicSharedMemorySize, SMEM_S);
        cudaFuncSetAttribute((const void*)mma_gemm_u<true, 1, 3>,  cudaFuncAttributeMaxDynamicSharedMemorySize, SMEM_D);
        cudaStreamCreateWithFlags(&s2, cudaStreamNonBlocking);
        cudaStreamCreateWithFlags(&s3, cudaStreamNonBlocking);
        cudaEventCreateWithFlags(&ev0, cudaEventDisableTiming);
        cudaEventCreateWithFlags(&ev1, cudaEventDisableTiming);
        cudaEventCreateWithFlags(&ev2, cudaEventDisableTiming);
        cudaEventCreateWithFlags(&ev3, cudaEventDisableTiming);
    }

    int n4 = NTOK * HDIM / 4;
    int w4 = IDIM * HDIM / 4;
    int r4 = NS * HDIM / 4;

    // ---- fork s3 from the capture stream FIRST (capture-legal), then its work ----
    cudaEventRecord(ev0, 0);
    cudaStreamWaitEvent(s3, ev0, 0);
    split_kernel<<<(w4 + 255) / 256, 256, 0, s3>>>(gate_w, gwh, gwl, w4);
    split_kernel<<<(w4 + 255) / 256, 256, 0, s3>>>(up_w,   uwh, uwl, w4);
    cudaEventRecord(ev3, s3);

    // ---- main stream: x split (needed by both branches) ----
    split_kernel<<<(n4 + 255) / 256, 256>>>(x, xh, xl, n4);
    cudaEventRecord(ev1, 0);
    cudaStreamWaitEvent(s2, ev1, 0);

    // ---- side stream s2: down_w split + router chain + expert gather ----
    split_kernel<<<(w4 + 255) / 256, 256, 0, s2>>>(down_w, dwh, dwl, w4);
    split_kernel<<<(r4 + 255) / 256, 256, 0, s2>>>(rxw, rwxh, rwxl, r4);
    split_kernel<<<(r4 + 255) / 256, 256, 0, s2>>>(ryw, rwyh, rwyl, r4);
    mma_gemm_u<false, 0, 4><<<dim3(1, NTOK / 128), 512, SMEM_S, s2>>>(
        xh, xl, rwxh, rwxl, nullptr, nullptr, nullptr, rx, nullptr, nullptr, HDIM, NS);
    mma_gemm_u<false, 0, 4><<<dim3(1, NTOK / 128), 512, SMEM_S, s2>>>(
        xh, xl, rwyh, rwyl, nullptr, nullptr, nullptr, ry, nullptr, nullptr, HDIM, NS);
    col_stats<<<2 * NS, 256, 0, s2>>>();
    bn_logsoftmax<<<NTOK, NS, 0, s2>>>();
    topk_kernel<<<NTOK, 32, 0, s2>>>();
    expert_kernel<<<NTOK, 256, 0, s2>>>(x, up_e, down_e);
    cudaEventRecord(ev2, s2);

    // ---- main stream: dense MLP ----
    cudaStreamWaitEvent(0, ev3, 0);
    // fused gate+up -> h (bf16 hi/lo)
    mma_gemm_u<true, 1, 3><<<dim3(IDIM / 128, NTOK / 128), 512, SMEM_D>>>(
        xh, xl, gwh, gwl, uwh, uwl, nullptr, nullptr, hh, hl, HDIM, IDIM);

    // join expert branch, then down GEMM with fused expert add
    cudaStreamWaitEvent(0, ev2, 0);
    mma_gemm_u<false, 2, 4><<<dim3(HDIM / 128, NTOK / 128), 512, SMEM_S>>>(
        hh, hl, dwh, dwl, nullptr, nullptr, eo, out, nullptr, nullptr, IDIM, HDIM);
}

// round 12
// speedup vs baseline: 1.3659x; 1.3175x over previous
#include <cuda_runtime.h>
#include <cuda_fp16.h>
#include <math.h>
#include <stdint.h>

#define NTOK 4096   // B*S
#define HDIM 1024
#define IDIM 4096
#define NS   128
#define TOPK 16
#define BN_EPS 1e-5f

typedef __half fp16;

// ================= scratch (static device allocations) =================
__device__ float g_rx[NTOK * NS];
__device__ float g_ry[NTOK * NS];
__device__ float g_mean[2 * NS];
__device__ float g_rstd[2 * NS];
__device__ int   g_idx[NTOK * TOPK];
__device__ float g_wk[NTOK * TOPK];
__device__ float g_eout[(size_t)NTOK * HDIM];
// fp16 operands: x and h as hi/lo pairs; weights hi-only (A-corrected 2-product);
// router weights hi/lo (3-product for exact top-k).
__device__ fp16 g_xh[NTOK * HDIM],  g_xl[NTOK * HDIM];
__device__ fp16 g_gwh[IDIM * HDIM];
__device__ fp16 g_uwh[IDIM * HDIM];
__device__ fp16 g_dwh[HDIM * IDIM];
__device__ fp16 g_rwxh[NS * HDIM], g_rwxl[NS * HDIM];
__device__ fp16 g_rwyh[NS * HDIM], g_rwyl[NS * HDIM];
__device__ fp16 g_hh[(size_t)NTOK * IDIM], g_hl[(size_t)NTOK * IDIM];

// ================= helpers =================
__device__ __forceinline__ uint32_t smem_to_u32(const void* p) {
    uint32_t a;
    asm("{ .reg .u64 t; cvta.to.shared.u64 t, %1; cvt.u32.u64 %0, t; }" : "=r"(a) : "l"(p));
    return a;
}

#define MMA16816(c, a, b) \
    asm volatile("mma.sync.aligned.m16n8k16.row.col.f32.f16.f16.f32 " \
        "{%0,%1,%2,%3}, {%4,%5,%6,%7}, {%8,%9}, {%0,%1,%2,%3};" \
        : "+f"((c)[0]), "+f"((c)[1]), "+f"((c)[2]), "+f"((c)[3]) \
        : "r"((a)[0]), "r"((a)[1]), "r"((a)[2]), "r"((a)[3]), "r"((b)[0]), "r"((b)[1]))

#define LDSM_X4(r, addr) \
    asm volatile("ldmatrix.sync.aligned.m8n8.x4.shared.b16 {%0,%1,%2,%3}, [%4];" \
        : "=r"((r)[0]), "=r"((r)[1]), "=r"((r)[2]), "=r"((r)[3]) : "r"(addr))

#define TILE_B 10240   // 128 rows * 80B (32 fp16 + 8B pad), conflict-free for ldmatrix

// ================= unified fp16 split-precision tensor-core GEMM =================
// C[M,N(128)] = (Ah+Al)[M,K] * B^T, fp32 accum.
//  BL=false (dense): B hi only, 2 products (ah*bh + al*bh)  -> err ~ 1.2e-4
//  BL=true (router): B hi/lo, 3 products (+ ah*bl)          -> err ~ 1e-6
// 512 threads = 16 warps (4x4 of 32x32 warp tiles), 128x128 CTA tile, BK=32,
// NST-stage cp.async pipeline. MODE 0: Cout=acc. MODE 2: Cout=acc+E.
// MODE 1 (DUAL): h=silu(g)*u -> fp16 hi/lo.
// Stage tile layout: [Ah, Al, B1h, (DUAL? B2h : (BL? B1l : --))]

template<bool DUAL, bool BL, int MODE, int NST>
__global__ __launch_bounds__(512, 1) void mma_gemm_u(
    const fp16* __restrict__ Ah, const fp16* __restrict__ Al,
    const fp16* __restrict__ B1h, const fp16* __restrict__ B1l,
    const fp16* __restrict__ B2h,
    const float* __restrict__ E, float* __restrict__ Cout,
    fp16* __restrict__ Hh, fp16* __restrict__ Hl, int K, int ldo)
{
    constexpr int NTILE = (DUAL || BL) ? 4 : 3;
    constexpr int STAGE = NTILE * TILE_B;
    extern __shared__ __align__(128) char smem[];
    const uint32_t sb = smem_to_u32(smem);
    const int tid = threadIdx.x;
    const int lane = tid & 31;
    const int warp = tid >> 5;
    const int warp_m = warp >> 2;      // 0..3
    const int warp_n = warp & 3;       // 0..3
    const int bm = blockIdx.y * 128, bn = blockIdx.x * 128;
    const int KC = K >> 5;

    float accg[2][4][4];
    float accu[2][4][4];
#pragma unroll
    for (int i = 0; i < 2; i++)
#pragma unroll
        for (int j = 0; j < 4; j++)
#pragma unroll
            for (int e = 0; e < 4; e++) { accg[i][j][e] = 0.f; if (DUAL) accu[i][j][e] = 0.f; }

    // 512 threads x 16B = 8KB = exactly one 128x32 fp16 tile per pass
    auto load_stage = [&](int st, int k0) {
        int r = tid >> 2, c = tid & 3;
        uint32_t sa0 = sb + st * STAGE + r * 80 + c * 16;
#pragma unroll
        for (int t = 0; t < NTILE; t++) {
            const fp16* src = (t == 0) ? Ah : (t == 1) ? Al : (t == 2) ? B1h :
                              (DUAL ? B2h : B1l);
            int row0 = (t < 2) ? bm : bn;
            const fp16* ga = src + (size_t)(row0 + r) * K + k0 + c * 8;
            asm volatile("cp.async.cg.shared.global [%0], [%1], 16;"
                         :: "r"(sa0 + t * TILE_B), "l"(ga));
        }
    };

#pragma unroll
    for (int p = 0; p < NST - 1; p++) {
        load_stage(p, p * 32);
        asm volatile("cp.async.commit_group;" ::: "memory");
    }

    int st_c = 0, st_l = NST - 1;
    for (int kc = 0; kc < KC; kc++) {
        asm volatile("cp.async.wait_group %0;" :: "n"(NST - 2) : "memory");
        __syncthreads();
        if (kc + NST - 1 < KC) load_stage(st_l, (kc + NST - 1) * 32);
        asm volatile("cp.async.commit_group;" ::: "memory");

        const uint32_t stage = sb + st_c * STAGE;
#pragma unroll
        for (int kk = 0; kk < 32; kk += 16) {
            uint32_t ah[2][4], al[2][4];
#pragma unroll
            for (int fm = 0; fm < 2; fm++) {
                int row = warp_m * 32 + fm * 16 + (lane & 15);
                int kw = kk + (lane >> 4) * 8;
                uint32_t a_addr = stage + row * 80 + kw * 2;
                LDSM_X4(ah[fm], a_addr);
                LDSM_X4(al[fm], a_addr + TILE_B);
            }
            int brow = warp_n * 32 + (lane & 15);
            int bkw = kk + (lane >> 4) * 8;
            // B1
            {
                uint32_t bh[4][2], bl[4][2];
#pragma unroll
                for (int fp = 0; fp < 2; fp++) {
                    uint32_t b_addr = stage + 2 * TILE_B + (brow + fp * 16) * 80 + bkw * 2;
                    uint32_t th[4];
                    LDSM_X4(th, b_addr);
                    bh[2 * fp][0] = th[0]; bh[2 * fp + 1][0] = th[1];
                    bh[2 * fp][1] = th[2]; bh[2 * fp + 1][1] = th[3];
                    if (BL) {
                        uint32_t tl[4];
                        LDSM_X4(tl, b_addr + TILE_B);
                        bl[2 * fp][0] = tl[0]; bl[2 * fp + 1][0] = tl[1];
                        bl[2 * fp][1] = tl[2]; bl[2 * fp + 1][1] = tl[3];
                    }
                }
#pragma unroll
                for (int fm = 0; fm < 2; fm++)
#pragma unroll
                    for (int fn = 0; fn < 4; fn++) {
                        MMA16816(accg[fm][fn], ah[fm], bh[fn]);
                        MMA16816(accg[fm][fn], al[fm], bh[fn]);
                        if (BL) MMA16816(accg[fm][fn], ah[fm], bl[fn]);
                    }
            }
            // B2 (dual only, hi-only)
            if (DUAL) {
                uint32_t bh[4][2];
#pragma unroll
                for (int fp = 0; fp < 2; fp++) {
                    uint32_t b_addr = stage + 3 * TILE_B + (brow + fp * 16) * 80 + bkw * 2;
                    uint32_t th[4];
                    LDSM_X4(th, b_addr);
                    bh[2 * fp][0] = th[0]; bh[2 * fp + 1][0] = th[1];
                    bh[2 * fp][1] = th[2]; bh[2 * fp + 1][1] = th[3];
                }
#pragma unroll
                for (int fm = 0; fm < 2; fm++)
#pragma unroll
                    for (int fn = 0; fn < 4; fn++) {
                        MMA16816(accu[fm][fn], ah[fm], bh[fn]);
                        MMA16816(accu[fm][fn], al[fm], bh[fn]);
                    }
            }
        }
        st_c++; if (st_c == NST) st_c = 0;
        st_l++; if (st_l == NST) st_l = 0;
    }

    // ---------------- epilogue ----------------
#pragma unroll
    for (int fm = 0; fm < 2; fm++)
#pragma unroll
        for (int fn = 0; fn < 4; fn++) {
            int row = bm + warp_m * 32 + fm * 16 + (lane >> 2);
            int col = bn + warp_n * 32 + fn * 8 + 2 * (lane & 3);
#pragma unroll
            for (int h = 0; h < 2; h++) {
                int r = row + h * 8;
                size_t off = (size_t)r * ldo + col;
                float d0 = accg[fm][fn][2 * h], d1 = accg[fm][fn][2 * h + 1];
                if (MODE == 1) {
                    float ux = accu[fm][fn][2 * h], uy = accu[fm][fn][2 * h + 1];
                    float h0 = d0 / (1.f + expf(-d0)) * ux;
                    float h1 = d1 / (1.f + expf(-d1)) * uy;
                    fp16 h0h = __float2half_rn(h0);
                    fp16 h1h = __float2half_rn(h1);
                    fp16 h0l = __float2half_rn(h0 - __half2float(h0h));
                    fp16 h1l = __float2half_rn(h1 - __half2float(h1h));
                    *(__half2*)(Hh + off) = __halves2half2(h0h, h1h);
                    *(__half2*)(Hl + off) = __halves2half2(h0l, h1l);
                } else {
                    if (MODE == 2) {
                        float2 e = *(const float2*)(E + off);
                        d0 += e.x; d1 += e.y;
                    }
                    *(float2*)(Cout + off) = make_float2(d0, d1);
                }
            }
        }
}

// ================= fp32 -> fp16 hi/lo split =================
__global__ void split2_kernel(const float* __restrict__ s, fp16* __restrict__ hi,
                              fp16* __restrict__ lo, int n4)
{
    int i = blockIdx.x * blockDim.x + threadIdx.x;
    if (i >= n4) return;
    float4 v = ((const float4*)s)[i];
    float vv[4] = {v.x, v.y, v.z, v.w};
    fp16 h[4], l[4];
#pragma unroll
    for (int j = 0; j < 4; j++) {
        h[j] = __float2half_rn(vv[j]);
        l[j] = __float2half_rn(vv[j] - __half2float(h[j]));
    }
    ((__half2*)hi)[2 * i]     = __halves2half2(h[0], h[1]);
    ((__half2*)hi)[2 * i + 1] = __halves2half2(h[2], h[3]);
    ((__half2*)lo)[2 * i]     = __halves2half2(l[0], l[1]);
    ((__half2*)lo)[2 * i + 1] = __halves2half2(l[2], l[3]);
}

// ================= fp32 -> fp16 (hi only, for dense weights) =================
__global__ void conv1_kernel(const float* __restrict__ s, fp16* __restrict__ hi, int n4)
{
    int i = blockIdx.x * blockDim.x + threadIdx.x;
    if (i >= n4) return;
    float4 v = ((const float4*)s)[i];
    ((__half2*)hi)[2 * i]     = __halves2half2(__float2half_rn(v.x), __float2half_rn(v.y));
    ((__half2*)hi)[2 * i + 1] = __halves2half2(__float2half_rn(v.z), __float2half_rn(v.w));
}

// ================= batch stats =================
__global__ void col_stats()
{
    const int c = blockIdx.x;
    const float* r = (c < NS) ? g_rx : g_ry;
    const int col = c & (NS - 1);
    float s = 0.f, s2 = 0.f;
    for (int i = threadIdx.x; i < NTOK; i += 256) {
        float v = r[i * NS + col];
        s += v; s2 += v * v;
    }
    __shared__ float sh[64];
#pragma unroll
    for (int o = 16; o; o >>= 1) {
        s  += __shfl_down_sync(0xffffffffu, s,  o);
        s2 += __shfl_down_sync(0xffffffffu, s2, o);
    }
    const int w = threadIdx.x >> 5;
    if ((threadIdx.x & 31) == 0) { sh[w] = s; sh[32 + w] = s2; }
    __syncthreads();
    if (threadIdx.x == 0) {
        float S = 0.f, S2 = 0.f;
        for (int i = 0; i < 8; i++) { S += sh[i]; S2 += sh[32 + i]; }
        float m = S / (float)NTOK;
        float var = S2 / (float)NTOK - m * m;
        g_mean[c] = m;
        g_rstd[c] = rsqrtf(var + BN_EPS);
    }
}

// ================= bn + log_softmax =================
__global__ void bn_logsoftmax()
{
    const int n = blockIdx.x;
    const int c = threadIdx.x;
    __shared__ float sh[4];
#pragma unroll
    for (int r = 0; r < 2; r++) {
        float* buf = r ? g_ry : g_rx;
        float z = (buf[n * NS + c] - g_mean[r * NS + c]) * g_rstd[r * NS + c];
        float v = z;
#pragma unroll
        for (int o = 16; o; o >>= 1) v = fmaxf(v, __shfl_xor_sync(0xffffffffu, v, o));
        if ((c & 31) == 0) sh[c >> 5] = v;
        __syncthreads();
        float m = fmaxf(fmaxf(sh[0], sh[1]), fmaxf(sh[2], sh[3]));
        __syncthreads();
        float e = expf(z - m), sv = e;
#pragma unroll
        for (int o = 16; o; o >>= 1) sv += __shfl_xor_sync(0xffffffffu, sv, o);
        if ((c & 31) == 0) sh[c >> 5] = sv;
        __syncthreads();
        float tot = sh[0] + sh[1] + sh[2] + sh[3];
        buf[n * NS + c] = z - (m + logf(tot));
        __syncthreads();
    }
}

// ================= product-key top-k =================
__global__ void topk_kernel()
{
    const int n = blockIdx.x;
    const int lane = threadIdx.x;
    __shared__ float sx[16], sy[16];
    __shared__ int sxi[16], syi[16];
    const float* rowx = g_rx + n * NS;
    const float* rowy = g_ry + n * NS;
    float vx[4], vy[4];
#pragma unroll
    for (int j = 0; j < 4; j++) { vx[j] = rowx[lane * 4 + j]; vy[j] = rowy[lane * 4 + j]; }

    for (int t = 0; t < 16; t++) {
        float bv = -INFINITY; int bj = 0;
#pragma unroll
        for (int j = 0; j < 4; j++) if (vx[j] > bv) { bv = vx[j]; bj = j; }
        int bl = lane;
#pragma unroll
        for (int o = 16; o; o >>= 1) {
            float ov = __shfl_down_sync(0xffffffffu, bv, o);
            int ol = __shfl_down_sync(0xffffffffu, bl, o);
            int oj = __shfl_down_sync(0xffffffffu, bj, o);
            if (ov > bv) { bv = ov; bl = ol; bj = oj; }
        }
        bv = __shfl_sync(0xffffffffu, bv, 0);
        bl = __shfl_sync(0xffffffffu, bl, 0);
        bj = __shfl_sync(0xffffffffu, bj, 0);
        if (lane == bl) {
#pragma unroll
            for (int j = 0; j < 4; j++) if (j == bj) vx[j] = -INFINITY;
        }
        if (lane == 0) { sx[t] = bv; sxi[t] = bl * 4 + bj; }
    }
    for (int t = 0; t < 16; t++) {
        float bv = -INFINITY; int bj = 0;
#pragma unroll
        for (int j = 0; j < 4; j++) if (vy[j] > bv) { bv = vy[j]; bj = j; }
        int bl = lane;
#pragma unroll
        for (int o = 16; o; o >>= 1) {
            float ov = __shfl_down_sync(0xffffffffu, bv, o);
            int ol = __shfl_down_sync(0xffffffffu, bl, o);
            int oj = __shfl_down_sync(0xffffffffu, bj, o);
            if (ov > bv) { bv = ov; bl = ol; bj = oj; }
        }
        bv = __shfl_sync(0xffffffffu, bv, 0);
        bl = __shfl_sync(0xffffffffu, bl, 0);
        bj = __shfl_sync(0xffffffffu, bj, 0);
        if (lane == bl) {
#pragma unroll
            for (int j = 0; j < 4; j++) if (j == bj) vy[j] = -INFINITY;
        }
        if (lane == 0) { sy[t] = bv; syi[t] = bl * 4 + bj; }
    }
    __syncwarp();

    float cv[8];
#pragma unroll
    for (int j = 0; j < 8; j++) {
        int p = lane * 8 + j;
        cv[j] = sx[p >> 4] + sy[p & 15];
    }
    for (int t = 0; t < 16; t++) {
        float bv = -INFINITY; int bj = 0;
#pragma unroll
        for (int j = 0; j < 8; j++) if (cv[j] > bv) { bv = cv[j]; bj = j; }
        int bl = lane;
#pragma unroll
        for (int o = 16; o; o >>= 1) {
            float ov = __shfl_down_sync(0xffffffffu, bv, o);
            int ol = __shfl_down_sync(0xffffffffu, bl, o);
            int oj = __shfl_down_sync(0xffffffffu, bj, o);
            if (ov > bv) { bv = ov; bl = ol; bj = oj; }
        }
        bv = __shfl_sync(0xffffffffu, bv, 0);
        bl = __shfl_sync(0xffffffffu, bl, 0);
        bj = __shfl_sync(0xffffffffu, bj, 0);
        if (lane == bl) {
#pragma unroll
            for (int j = 0; j < 8; j++) if (j == bj) cv[j] = -INFINITY;
        }
        if (lane == 0) {
            int p = bl * 8 + bj;
            g_idx[n * TOPK + t] = sxi[p >> 4] * NS + syi[p & 15];
            g_wk[n * TOPK + t] = expf(bv);
        }
    }
}

// ================= expert gather (writes g_eout) =================
__global__ __launch_bounds__(256) void expert_kernel(
    const float* __restrict__ x,
    const float* __restrict__ up_e,
    const float* __restrict__ down_e)
{
    const int n = blockIdx.x;
    __shared__ float sx[HDIM];
    __shared__ float sew[TOPK];
    const int tid = threadIdx.x;
    for (int i = tid; i < HDIM; i += 256) sx[i] = x[(size_t)n * HDIM + i];
    __syncthreads();
    const int warp = tid >> 5, lane = tid & 31;
#pragma unroll
    for (int k = warp; k < TOPK; k += 8) {
        int e = g_idx[n * TOPK + k];
        const float* ue = up_e + (size_t)e * HDIM;
        float d = 0.f;
#pragma unroll
        for (int i = lane * 4; i < HDIM; i += 128) {
            float4 u = *(const float4*)(ue + i);
            d += u.x * sx[i] + u.y * sx[i + 1] + u.z * sx[i + 2] + u.w * sx[i + 3];
        }
#pragma unroll
        for (int o = 16; o; o >>= 1) d += __shfl_down_sync(0xffffffffu, d, o);
        if (lane == 0) {
            float s = d / (1.f + expf(-d));
            sew[k] = s * g_wk[n * TOPK + k];
        }
    }
    __syncthreads();
    float acc[4] = {0.f, 0.f, 0.f, 0.f};
#pragma unroll
    for (int k = 0; k < TOPK; k++) {
        int e = g_idx[n * TOPK + k];
        float wk = sew[k];
        const float* de = down_e + (size_t)e * HDIM;
#pragma unroll
        for (int j = 0; j < 4; j++) acc[j] += wk * de[tid + j * 256];
    }
#pragma unroll
    for (int j = 0; j < 4; j++)
        g_eout[(size_t)n * HDIM + tid + j * 256] = acc[j];
}

// ================= launch =================
extern "C" void kernel_launch(void* const* d_in, const int* in_sizes, int n_in,
                              void* d_out, int out_size)
{
    const float* x      = (const float*)d_in[0];
    const float* gate_w = (const float*)d_in[1];
    const float* up_w   = (const float*)d_in[2];
    const float* down_w = (const float*)d_in[3];
    const float* rxw    = (const float*)d_in[4];
    const float* ryw    = (const float*)d_in[5];
    const float* up_e   = (const float*)d_in[6];
    const float* down_e = (const float*)d_in[7];
    float* out = (float*)d_out;

    float *rx, *ry, *eo;
    cudaGetSymbolAddress((void**)&rx, g_rx);
    cudaGetSymbolAddress((void**)&ry, g_ry);
    cudaGetSymbolAddress((void**)&eo, g_eout);
    fp16 *xh, *xl, *gwh, *uwh, *dwh, *hh, *hl;
    fp16 *rwxh, *rwxl, *rwyh, *rwyl;
    cudaGetSymbolAddress((void**)&xh, g_xh);   cudaGetSymbolAddress((void**)&xl, g_xl);
    cudaGetSymbolAddress((void**)&gwh, g_gwh);
    cudaGetSymbolAddress((void**)&uwh, g_uwh);
    cudaGetSymbolAddress((void**)&dwh, g_dwh);
    cudaGetSymbolAddress((void**)&rwxh, g_rwxh); cudaGetSymbolAddress((void**)&rwxl, g_rwxl);
    cudaGetSymbolAddress((void**)&rwyh, g_rwyh); cudaGetSymbolAddress((void**)&rwyl, g_rwyl);
    cudaGetSymbolAddress((void**)&hh, g_hh);   cudaGetSymbolAddress((void**)&hl, g_hl);

    const int SMEM_R = 4 * 4 * TILE_B;   // router: 4 tiles x 4 stages = 163840
    const int SMEM_D = 4 * 4 * TILE_B;   // dual:   4 tiles x 4 stages = 163840
    const int SMEM_S = 4 * 3 * TILE_B;   // down:   3 tiles x 4 stages = 122880
    static cudaStream_t s2 = nullptr, s3 = nullptr;
    static cudaEvent_t ev0 = nullptr, ev1 = nullptr, ev2 = nullptr, ev3 = nullptr;
    if (!s2) {
        cudaFuncSetAttribute((const void*)mma_gemm_u<false, true,  0, 4>, cudaFuncAttributeMaxDynamicSharedMemorySize, SMEM_R);
        cudaFuncSetAttribute((const void*)mma_gemm_u<true,  false, 1, 4>, cudaFuncAttributeMaxDynamicSharedMemorySize, SMEM_D);
        cudaFuncSetAttribute((const void*)mma_gemm_u<false, false, 2, 4>, cudaFuncAttributeMaxDynamicSharedMemorySize, SMEM_S);
        cudaStreamCreateWithFlags(&s2, cudaStreamNonBlocking);
        cudaStreamCreateWithFlags(&s3, cudaStreamNonBlocking);
        cudaEventCreateWithFlags(&ev0, cudaEventDisableTiming);
        cudaEventCreateWithFlags(&ev1, cudaEventDisableTiming);
        cudaEventCreateWithFlags(&ev2, cudaEventDisableTiming);
        cudaEventCreateWithFlags(&ev3, cudaEventDisableTiming);
    }

    int n4 = NTOK * HDIM / 4;
    int w4 = IDIM * HDIM / 4;
    int r4 = NS * HDIM / 4;

    // ---- fork s3 from the capture stream FIRST (capture-legal), then its work ----
    cudaEventRecord(ev0, 0);
    cudaStreamWaitEvent(s3, ev0, 0);
    conv1_kernel<<<(w4 + 255) / 256, 256, 0, s3>>>(gate_w, gwh, w4);
    conv1_kernel<<<(w4 + 255) / 256, 256, 0, s3>>>(up_w,   uwh, w4);
    cudaEventRecord(ev3, s3);

    // ---- main stream: x split (needed by both branches) ----
    split2_kernel<<<(n4 + 255) / 256, 256>>>(x, xh, xl, n4);
    cudaEventRecord(ev1, 0);
    cudaStreamWaitEvent(s2, ev1, 0);

    // ---- side stream s2: down_w conv + router chain + expert gather ----
    conv1_kernel<<<(w4 + 255) / 256, 256, 0, s2>>>(down_w, dwh, w4);
    split2_kernel<<<(r4 + 255) / 256, 256, 0, s2>>>(rxw, rwxh, rwxl, r4);
    split2_kernel<<<(r4 + 255) / 256, 256, 0, s2>>>(ryw, rwyh, rwyl, r4);
    mma_gemm_u<false, true, 0, 4><<<dim3(1, NTOK / 128), 512, SMEM_R, s2>>>(
        xh, xl, rwxh, rwxl, nullptr, nullptr, rx, nullptr, nullptr, HDIM, NS);
    mma_gemm_u<false, true, 0, 4><<<dim3(1, NTOK / 128), 512, SMEM_R, s2>>>(
        xh, xl, rwyh, rwyl, nullptr, nullptr, ry, nullptr, nullptr, HDIM, NS);
    col_stats<<<2 * NS, 256, 0, s2>>>();
    bn_logsoftmax<<<NTOK, NS, 0, s2>>>();
    topk_kernel<<<NTOK, 32, 0, s2>>>();
    expert_kernel<<<NTOK, 256, 0, s2>>>(x, up_e, down_e);
    cudaEventRecord(ev2, s2);

    // ---- main stream: dense MLP ----
    cudaStreamWaitEvent(0, ev3, 0);
    // fused gate+up -> h (fp16 hi/lo)
    mma_gemm_u<true, false, 1, 4><<<dim3(IDIM / 128, NTOK / 128), 512, SMEM_D>>>(
        xh, xl, gwh, nullptr, uwh, nullptr, nullptr, hh, hl, HDIM, IDIM);

    // join expert branch, then down GEMM with fused expert add
    cudaStreamWaitEvent(0, ev2, 0);
    mma_gemm_u<false, false, 2, 4><<<dim3(HDIM / 128, NTOK / 128), 512, SMEM_S>>>(
        hh, hl, dwh, nullptr, nullptr, eo, out, nullptr, nullptr, IDIM, HDIM);
}

// round 13
// speedup vs baseline: 1.6005x; 1.1717x over previous
#include <cuda_runtime.h>
#include <cuda_fp16.h>
#include <math.h>
#include <stdint.h>

#define NTOK 4096   // B*S
#define HDIM 1024
#define IDIM 4096
#define NS   128
#define TOPK 16
#define BN_EPS 1e-5f

typedef __half fp16;

// ================= scratch (static device allocations) =================
__device__ float g_rx[NTOK * NS];
__device__ float g_ry[NTOK * NS];
__device__ float g_mean[2 * NS];
__device__ float g_rstd[2 * NS];
__device__ int   g_idx[NTOK * TOPK];
__device__ float g_wk[NTOK * TOPK];
__device__ float g_eout[(size_t)NTOK * HDIM];
// fp16 operands: x hi/lo; dense weights hi-only; router weights hi/lo; h hi-only.
__device__ fp16 g_xh[NTOK * HDIM],  g_xl[NTOK * HDIM];
__device__ fp16 g_gwh[IDIM * HDIM];
__device__ fp16 g_uwh[IDIM * HDIM];
__device__ fp16 g_dwh[HDIM * IDIM];
__device__ fp16 g_rwxh[NS * HDIM], g_rwxl[NS * HDIM];
__device__ fp16 g_rwyh[NS * HDIM], g_rwyl[NS * HDIM];
__device__ fp16 g_hh[(size_t)NTOK * IDIM];

// ================= helpers =================
__device__ __forceinline__ uint32_t smem_to_u32(const void* p) {
    uint32_t a;
    asm("{ .reg .u64 t; cvta.to.shared.u64 t, %1; cvt.u32.u64 %0, t; }" : "=r"(a) : "l"(p));
    return a;
}

#define MMA16816(c, a, b) \
    asm volatile("mma.sync.aligned.m16n8k16.row.col.f32.f16.f16.f32 " \
        "{%0,%1,%2,%3}, {%4,%5,%6,%7}, {%8,%9}, {%0,%1,%2,%3};" \
        : "+f"((c)[0]), "+f"((c)[1]), "+f"((c)[2]), "+f"((c)[3]) \
        : "r"((a)[0]), "r"((a)[1]), "r"((a)[2]), "r"((a)[3]), "r"((b)[0]), "r"((b)[1]))

#define LDSM_X4(r, addr) \
    asm volatile("ldmatrix.sync.aligned.m8n8.x4.shared.b16 {%0,%1,%2,%3}, [%4];" \
        : "=r"((r)[0]), "=r"((r)[1]), "=r"((r)[2]), "=r"((r)[3]) : "r"(addr))

#define TILE_B 10240   // 128 rows * 80B (32 fp16 + 8B pad), conflict-free for ldmatrix

// ================= unified fp16 split-precision tensor-core GEMM =================
// C[M,N(128)] = A[M,K] * B^T, fp32 accum.
//  AL: A has lo correction (products ah*bh + al*bh)
//  BL: B has lo correction (adds ah*bl)  -- router only (exact top-k)
//  AL=false, BL=false: plain fp16 1-product (down GEMM: A=h already fp16-exact)
// 512 threads = 16 warps (4x4 of 32x32 warp tiles), 128x128 CTA tile, BK=32,
// NST-stage cp.async pipeline. MODE 0: Cout=acc. MODE 2: Cout=acc+E.
// MODE 1 (DUAL): h=silu(g)*u -> fp16 (hi only).
// Stage tile layout: [Ah, (AL? Al), B1h, (DUAL? B2h : BL? B1l)]

template<bool DUAL, bool BL, bool AL, int MODE, int NST>
__global__ __launch_bounds__(512, 1) void mma_gemm_u(
    const fp16* __restrict__ Ah, const fp16* __restrict__ Al,
    const fp16* __restrict__ B1h, const fp16* __restrict__ B1l,
    const fp16* __restrict__ B2h,
    const float* __restrict__ E, float* __restrict__ Cout,
    fp16* __restrict__ Hh, int K, int ldo)
{
    constexpr int NA = AL ? 2 : 1;
    constexpr int NTILE = NA + 1 + ((DUAL || BL) ? 1 : 0);
    constexpr int STAGE = NTILE * TILE_B;
    constexpr uint32_t OFF_B1 = NA * TILE_B;
    constexpr uint32_t OFF_B2 = OFF_B1 + TILE_B;   // B2h or B1l
    extern __shared__ __align__(128) char smem[];
    const uint32_t sb = smem_to_u32(smem);
    const int tid = threadIdx.x;
    const int lane = tid & 31;
    const int warp = tid >> 5;
    const int warp_m = warp >> 2;      // 0..3
    const int warp_n = warp & 3;       // 0..3
    const int bm = blockIdx.y * 128, bn = blockIdx.x * 128;
    const int KC = K >> 5;

    float accg[2][4][4];
    float accu[2][4][4];
#pragma unroll
    for (int i = 0; i < 2; i++)
#pragma unroll
        for (int j = 0; j < 4; j++)
#pragma unroll
            for (int e = 0; e < 4; e++) { accg[i][j][e] = 0.f; if (DUAL) accu[i][j][e] = 0.f; }

    // 512 threads x 16B = 8KB = exactly one 128x32 fp16 tile per pass
    auto load_stage = [&](int st, int k0) {
        int r = tid >> 2, c = tid & 3;
        uint32_t sa0 = sb + st * STAGE + r * 80 + c * 16;
#pragma unroll
        for (int t = 0; t < NTILE; t++) {
            const fp16* src;
            if (t == 0) src = Ah;
            else if (AL && t == 1) src = Al;
            else if (t == NA) src = B1h;
            else src = DUAL ? B2h : B1l;
            int row0 = (t < NA) ? bm : bn;
            const fp16* ga = src + (size_t)(row0 + r) * K + k0 + c * 8;
            asm volatile("cp.async.cg.shared.global [%0], [%1], 16;"
                         :: "r"(sa0 + t * TILE_B), "l"(ga));
        }
    };

#pragma unroll
    for (int p = 0; p < NST - 1; p++) {
        load_stage(p, p * 32);
        asm volatile("cp.async.commit_group;" ::: "memory");
    }

    int st_c = 0, st_l = NST - 1;
    for (int kc = 0; kc < KC; kc++) {
        asm volatile("cp.async.wait_group %0;" :: "n"(NST - 2) : "memory");
        __syncthreads();
        if (kc + NST - 1 < KC) load_stage(st_l, (kc + NST - 1) * 32);
        asm volatile("cp.async.commit_group;" ::: "memory");

        const uint32_t stage = sb + st_c * STAGE;
#pragma unroll
        for (int kk = 0; kk < 32; kk += 16) {
            uint32_t ah[2][4], al[2][4];
#pragma unroll
            for (int fm = 0; fm < 2; fm++) {
                int row = warp_m * 32 + fm * 16 + (lane & 15);
                int kw = kk + (lane >> 4) * 8;
                uint32_t a_addr = stage + row * 80 + kw * 2;
                LDSM_X4(ah[fm], a_addr);
                if (AL) LDSM_X4(al[fm], a_addr + TILE_B);
            }
            int brow = warp_n * 32 + (lane & 15);
            int bkw = kk + (lane >> 4) * 8;
            // B1
            {
                uint32_t bh[4][2], bl[4][2];
#pragma unroll
                for (int fp = 0; fp < 2; fp++) {
                    uint32_t b_addr = stage + OFF_B1 + (brow + fp * 16) * 80 + bkw * 2;
                    uint32_t th[4];
                    LDSM_X4(th, b_addr);
                    bh[2 * fp][0] = th[0]; bh[2 * fp + 1][0] = th[1];
                    bh[2 * fp][1] = th[2]; bh[2 * fp + 1][1] = th[3];
                    if (BL) {
                        uint32_t tl[4];
                        LDSM_X4(tl, b_addr + TILE_B);
                        bl[2 * fp][0] = tl[0]; bl[2 * fp + 1][0] = tl[1];
                        bl[2 * fp][1] = tl[2]; bl[2 * fp + 1][1] = tl[3];
                    }
                }
#pragma unroll
                for (int fm = 0; fm < 2; fm++)
#pragma unroll
                    for (int fn = 0; fn < 4; fn++) {
                        MMA16816(accg[fm][fn], ah[fm], bh[fn]);
                        if (AL) MMA16816(accg[fm][fn], al[fm], bh[fn]);
                        if (BL) MMA16816(accg[fm][fn], ah[fm], bl[fn]);
                    }
            }
            // B2 (dual only, hi-only)
            if (DUAL) {
                uint32_t bh[4][2];
#pragma unroll
                for (int fp = 0; fp < 2; fp++) {
                    uint32_t b_addr = stage + OFF_B2 + (brow + fp * 16) * 80 + bkw * 2;
                    uint32_t th[4];
                    LDSM_X4(th, b_addr);
                    bh[2 * fp][0] = th[0]; bh[2 * fp + 1][0] = th[1];
                    bh[2 * fp][1] = th[2]; bh[2 * fp + 1][1] = th[3];
                }
#pragma unroll
                for (int fm = 0; fm < 2; fm++)
#pragma unroll
                    for (int fn = 0; fn < 4; fn++) {
                        MMA16816(accu[fm][fn], ah[fm], bh[fn]);
                        if (AL) MMA16816(accu[fm][fn], al[fm], bh[fn]);
                    }
            }
        }
        st_c++; if (st_c == NST) st_c = 0;
        st_l++; if (st_l == NST) st_l = 0;
    }

    // ---------------- epilogue ----------------
#pragma unroll
    for (int fm = 0; fm < 2; fm++)
#pragma unroll
        for (int fn = 0; fn < 4; fn++) {
            int row = bm + warp_m * 32 + fm * 16 + (lane >> 2);
            int col = bn + warp_n * 32 + fn * 8 + 2 * (lane & 3);
#pragma unroll
            for (int h = 0; h < 2; h++) {
                int r = row + h * 8;
                size_t off = (size_t)r * ldo + col;
                float d0 = accg[fm][fn][2 * h], d1 = accg[fm][fn][2 * h + 1];
                if (MODE == 1) {
                    float ux = accu[fm][fn][2 * h], uy = accu[fm][fn][2 * h + 1];
                    float h0 = d0 / (1.f + expf(-d0)) * ux;
                    float h1 = d1 / (1.f + expf(-d1)) * uy;
                    *(__half2*)(Hh + off) =
                        __halves2half2(__float2half_rn(h0), __float2half_rn(h1));
                } else {
                    if (MODE == 2) {
                        float2 e = *(const float2*)(E + off);
                        d0 += e.x; d1 += e.y;
                    }
                    *(float2*)(Cout + off) = make_float2(d0, d1);
                }
            }
        }
}

// ================= fp32 -> fp16 hi/lo split =================
__global__ void split2_kernel(const float* __restrict__ s, fp16* __restrict__ hi,
                              fp16* __restrict__ lo, int n4)
{
    int i = blockIdx.x * blockDim.x + threadIdx.x;
    if (i >= n4) return;
    float4 v = ((const float4*)s)[i];
    float vv[4] = {v.x, v.y, v.z, v.w};
    fp16 h[4], l[4];
#pragma unroll
    for (int j = 0; j < 4; j++) {
        h[j] = __float2half_rn(vv[j]);
        l[j] = __float2half_rn(vv[j] - __half2float(h[j]));
    }
    ((__half2*)hi)[2 * i]     = __halves2half2(h[0], h[1]);
    ((__half2*)hi)[2 * i + 1] = __halves2half2(h[2], h[3]);
    ((__half2*)lo)[2 * i]     = __halves2half2(l[0], l[1]);
    ((__half2*)lo)[2 * i + 1] = __halves2half2(l[2], l[3]);
}

// ================= fp32 -> fp16 (hi only, for dense weights) =================
__global__ void conv1_kernel(const float* __restrict__ s, fp16* __restrict__ hi, int n4)
{
    int i = blockIdx.x * blockDim.x + threadIdx.x;
    if (i >= n4) return;
    float4 v = ((const float4*)s)[i];
    ((__half2*)hi)[2 * i]     = __halves2half2(__float2half_rn(v.x), __float2half_rn(v.y));
    ((__half2*)hi)[2 * i + 1] = __halves2half2(__float2half_rn(v.z), __float2half_rn(v.w));
}

// ================= batch stats =================
__global__ void col_stats()
{
    const int c = blockIdx.x;
    const float* r = (c < NS) ? g_rx : g_ry;
    const int col = c & (NS - 1);
    float s = 0.f, s2 = 0.f;
    for (int i = threadIdx.x; i < NTOK; i += 256) {
        float v = r[i * NS + col];
        s += v; s2 += v * v;
    }
    __shared__ float sh[64];
#pragma unroll
    for (int o = 16; o; o >>= 1) {
        s  += __shfl_down_sync(0xffffffffu, s,  o);
        s2 += __shfl_down_sync(0xffffffffu, s2, o);
    }
    const int w = threadIdx.x >> 5;
    if ((threadIdx.x & 31) == 0) { sh[w] = s; sh[32 + w] = s2; }
    __syncthreads();
    if (threadIdx.x == 0) {
        float S = 0.f, S2 = 0.f;
        for (int i = 0; i < 8; i++) { S += sh[i]; S2 += sh[32 + i]; }
        float m = S / (float)NTOK;
        float var = S2 / (float)NTOK - m * m;
        g_mean[c] = m;
        g_rstd[c] = rsqrtf(var + BN_EPS);
    }
}

// ================= bn + log_softmax =================
__global__ void bn_logsoftmax()
{
    const int n = blockIdx.x;
    const int c = threadIdx.x;
    __shared__ float sh[4];
#pragma unroll
    for (int r = 0; r < 2; r++) {
        float* buf = r ? g_ry : g_rx;
        float z = (buf[n * NS + c] - g_mean[r * NS + c]) * g_rstd[r * NS + c];
        float v = z;
#pragma unroll
        for (int o = 16; o; o >>= 1) v = fmaxf(v, __shfl_xor_sync(0xffffffffu, v, o));
        if ((c & 31) == 0) sh[c >> 5] = v;
        __syncthreads();
        float m = fmaxf(fmaxf(sh[0], sh[1]), fmaxf(sh[2], sh[3]));
        __syncthreads();
        float e = expf(z - m), sv = e;
#pragma unroll
        for (int o = 16; o; o >>= 1) sv += __shfl_xor_sync(0xffffffffu, sv, o);
        if ((c & 31) == 0) sh[c >> 5] = sv;
        __syncthreads();
        float tot = sh[0] + sh[1] + sh[2] + sh[3];
        buf[n * NS + c] = z - (m + logf(tot));
        __syncthreads();
    }
}

// ================= product-key top-k =================
__global__ void topk_kernel()
{
    const int n = blockIdx.x;
    const int lane = threadIdx.x;
    __shared__ float sx[16], sy[16];
    __shared__ int sxi[16], syi[16];
    const float* rowx = g_rx + n * NS;
    const float* rowy = g_ry + n * NS;
    float vx[4], vy[4];
#pragma unroll
    for (int j = 0; j < 4; j++) { vx[j] = rowx[lane * 4 + j]; vy[j] = rowy[lane * 4 + j]; }

    for (int t = 0; t < 16; t++) {
        float bv = -INFINITY; int bj = 0;
#pragma unroll
        for (int j = 0; j < 4; j++) if (vx[j] > bv) { bv = vx[j]; bj = j; }
        int bl = lane;
#pragma unroll
        for (int o = 16; o; o >>= 1) {
            float ov = __shfl_down_sync(0xffffffffu, bv, o);
            int ol = __shfl_down_sync(0xffffffffu, bl, o);
            int oj = __shfl_down_sync(0xffffffffu, bj, o);
            if (ov > bv) { bv = ov; bl = ol; bj = oj; }
        }
        bv = __shfl_sync(0xffffffffu, bv, 0);
        bl = __shfl_sync(0xffffffffu, bl, 0);
        bj = __shfl_sync(0xffffffffu, bj, 0);
        if (lane == bl) {
#pragma unroll
            for (int j = 0; j < 4; j++) if (j == bj) vx[j] = -INFINITY;
        }
        if (lane == 0) { sx[t] = bv; sxi[t] = bl * 4 + bj; }
    }
    for (int t = 0; t < 16; t++) {
        float bv = -INFINITY; int bj = 0;
#pragma unroll
        for (int j = 0; j < 4; j++) if (vy[j] > bv) { bv = vy[j]; bj = j; }
        int bl = lane;
#pragma unroll
        for (int o = 16; o; o >>= 1) {
            float ov = __shfl_down_sync(0xffffffffu, bv, o);
            int ol = __shfl_down_sync(0xffffffffu, bl, o);
            int oj = __shfl_down_sync(0xffffffffu, bj, o);
            if (ov > bv) { bv = ov; bl = ol; bj = oj; }
        }
        bv = __shfl_sync(0xffffffffu, bv, 0);
        bl = __shfl_sync(0xffffffffu, bl, 0);
        bj = __shfl_sync(0xffffffffu, bj, 0);
        if (lane == bl) {
#pragma unroll
            for (int j = 0; j < 4; j++) if (j == bj) vy[j] = -INFINITY;
        }
        if (lane == 0) { sy[t] = bv; syi[t] = bl * 4 + bj; }
    }
    __syncwarp();

    float cv[8];
#pragma unroll
    for (int j = 0; j < 8; j++) {
        int p = lane * 8 + j;
        cv[j] = sx[p >> 4] + sy[p & 15];
    }
    for (int t = 0; t < 16; t++) {
        float bv = -INFINITY; int bj = 0;
#pragma unroll
        for (int j = 0; j < 8; j++) if (cv[j] > bv) { bv = cv[j]; bj = j; }
        int bl = lane;
#pragma unroll
        for (int o = 16; o; o >>= 1) {
            float ov = __shfl_down_sync(0xffffffffu, bv, o);
            int ol = __shfl_down_sync(0xffffffffu, bl, o);
            int oj = __shfl_down_sync(0xffffffffu, bj, o);
            if (ov > bv) { bv = ov; bl = ol; bj = oj; }
        }
        bv = __shfl_sync(0xffffffffu, bv, 0);
        bl = __shfl_sync(0xffffffffu, bl, 0);
        bj = __shfl_sync(0xffffffffu, bj, 0);
        if (lane == bl) {
#pragma unroll
            for (int j = 0; j < 8; j++) if (j == bj) cv[j] = -INFINITY;
        }
        if (lane == 0) {
            int p = bl * 8 + bj;
            g_idx[n * TOPK + t] = sxi[p >> 4] * NS + syi[p & 15];
            g_wk[n * TOPK + t] = expf(bv);
        }
    }
}

// ================= expert gather (writes g_eout) =================
__global__ __launch_bounds__(256) void expert_kernel(
    const float* __restrict__ x,
    const float* __restrict__ up_e,
    const float* __restrict__ down_e)
{
    const int n = blockIdx.x;
    __shared__ float sx[HDIM];
    __shared__ float sew[TOPK];
    const int tid = threadIdx.x;
    for (int i = tid; i < HDIM; i += 256) sx[i] = x[(size_t)n * HDIM + i];
    __syncthreads();
    const int warp = tid >> 5, lane = tid & 31;
#pragma unroll
    for (int k = warp; k < TOPK; k += 8) {
        int e = g_idx[n * TOPK + k];
        const float* ue = up_e + (size_t)e * HDIM;
        float d = 0.f;
#pragma unroll
        for (int i = lane * 4; i < HDIM; i += 128) {
            float4 u = *(const float4*)(ue + i);
            d += u.x * sx[i] + u.y * sx[i + 1] + u.z * sx[i + 2] + u.w * sx[i + 3];
        }
#pragma unroll
        for (int o = 16; o; o >>= 1) d += __shfl_down_sync(0xffffffffu, d, o);
        if (lane == 0) {
            float s = d / (1.f + expf(-d));
            sew[k] = s * g_wk[n * TOPK + k];
        }
    }
    __syncthreads();
    float acc[4] = {0.f, 0.f, 0.f, 0.f};
#pragma unroll
    for (int k = 0; k < TOPK; k++) {
        int e = g_idx[n * TOPK + k];
        float wk = sew[k];
        const float* de = down_e + (size_t)e * HDIM;
#pragma unroll
        for (int j = 0; j < 4; j++) acc[j] += wk * de[tid + j * 256];
    }
#pragma unroll
    for (int j = 0; j < 4; j++)
        g_eout[(size_t)n * HDIM + tid + j * 256] = acc[j];
}

// ================= launch =================
extern "C" void kernel_launch(void* const* d_in, const int* in_sizes, int n_in,
                              void* d_out, int out_size)
{
    const float* x      = (const float*)d_in[0];
    const float* gate_w = (const float*)d_in[1];
    const float* up_w   = (const float*)d_in[2];
    const float* down_w = (const float*)d_in[3];
    const float* rxw    = (const float*)d_in[4];
    const float* ryw    = (const float*)d_in[5];
    const float* up_e   = (const float*)d_in[6];
    const float* down_e = (const float*)d_in[7];
    float* out = (float*)d_out;

    float *rx, *ry, *eo;
    cudaGetSymbolAddress((void**)&rx, g_rx);
    cudaGetSymbolAddress((void**)&ry, g_ry);
    cudaGetSymbolAddress((void**)&eo, g_eout);
    fp16 *xh, *xl, *gwh, *uwh, *dwh, *hh;
    fp16 *rwxh, *rwxl, *rwyh, *rwyl;
    cudaGetSymbolAddress((void**)&xh, g_xh);   cudaGetSymbolAddress((void**)&xl, g_xl);
    cudaGetSymbolAddress((void**)&gwh, g_gwh);
    cudaGetSymbolAddress((void**)&uwh, g_uwh);
    cudaGetSymbolAddress((void**)&dwh, g_dwh);
    cudaGetSymbolAddress((void**)&rwxh, g_rwxh); cudaGetSymbolAddress((void**)&rwxl, g_rwxl);
    cudaGetSymbolAddress((void**)&rwyh, g_rwyh); cudaGetSymbolAddress((void**)&rwyl, g_rwyl);
    cudaGetSymbolAddress((void**)&hh, g_hh);

    const int SMEM_R = 4 * 4 * TILE_B;   // router: 4 tiles x 4 stages = 163840
    const int SMEM_D = 4 * 4 * TILE_B;   // dual:   4 tiles x 4 stages = 163840
    const int SMEM_S = 6 * 2 * TILE_B;   // down:   2 tiles x 6 stages = 122880
    static cudaStream_t s2 = nullptr, s3 = nullptr;
    static cudaEvent_t ev0 = nullptr, ev1 = nullptr, ev2 = nullptr, ev3 = nullptr;
    if (!s2) {
        cudaFuncSetAttribute((const void*)mma_gemm_u<false, true,  true,  0, 4>, cudaFuncAttributeMaxDynamicSharedMemorySize, SMEM_R);
        cudaFuncSetAttribute((const void*)mma_gemm_u<true,  false, true,  1, 4>, cudaFuncAttributeMaxDynamicSharedMemorySize, SMEM_D);
        cudaFuncSetAttribute((const void*)mma_gemm_u<false, false, false, 2, 6>, cudaFuncAttributeMaxDynamicSharedMemorySize, SMEM_S);
        cudaStreamCreateWithFlags(&s2, cudaStreamNonBlocking);
        cudaStreamCreateWithFlags(&s3, cudaStreamNonBlocking);
        cudaEventCreateWithFlags(&ev0, cudaEventDisableTiming);
        cudaEventCreateWithFlags(&ev1, cudaEventDisableTiming);
        cudaEventCreateWithFlags(&ev2, cudaEventDisableTiming);
        cudaEventCreateWithFlags(&ev3, cudaEventDisableTiming);
    }

    int n4 = NTOK * HDIM / 4;
    int w4 = IDIM * HDIM / 4;
    int r4 = NS * HDIM / 4;

    // ---- fork s3 from the capture stream FIRST (capture-legal), then its work ----
    cudaEventRecord(ev0, 0);
    cudaStreamWaitEvent(s3, ev0, 0);
    conv1_kernel<<<(w4 + 255) / 256, 256, 0, s3>>>(gate_w, gwh, w4);
    conv1_kernel<<<(w4 + 255) / 256, 256, 0, s3>>>(up_w,   uwh, w4);
    cudaEventRecord(ev3, s3);

    // ---- main stream: x split (needed by both branches) ----
    split2_kernel<<<(n4 + 255) / 256, 256>>>(x, xh, xl, n4);
    cudaEventRecord(ev1, 0);
    cudaStreamWaitEvent(s2, ev1, 0);

    // ---- side stream s2: down_w conv + router chain + expert gather ----
    conv1_kernel<<<(w4 + 255) / 256, 256, 0, s2>>>(down_w, dwh, w4);
    split2_kernel<<<(r4 + 255) / 256, 256, 0, s2>>>(rxw, rwxh, rwxl, r4);
    split2_kernel<<<(r4 + 255) / 256, 256, 0, s2>>>(ryw, rwyh, rwyl, r4);
    mma_gemm_u<false, true, true, 0, 4><<<dim3(1, NTOK / 128), 512, SMEM_R, s2>>>(
        xh, xl, rwxh, rwxl, nullptr, nullptr, rx, nullptr, HDIM, NS);
    mma_gemm_u<false, true, true, 0, 4><<<dim3(1, NTOK / 128), 512, SMEM_R, s2>>>(
        xh, xl, rwyh, rwyl, nullptr, nullptr, ry, nullptr, HDIM, NS);
    col_stats<<<2 * NS, 256, 0, s2>>>();
    bn_logsoftmax<<<NTOK, NS, 0, s2>>>();
    topk_kernel<<<NTOK, 32, 0, s2>>>();
    expert_kernel<<<NTOK, 256, 0, s2>>>(x, up_e, down_e);
    cudaEventRecord(ev2, s2);

    // ---- main stream: dense MLP ----
    cudaStreamWaitEvent(0, ev3, 0);
    // fused gate+up -> h (fp16 hi only)
    mma_gemm_u<true, false, true, 1, 4><<<dim3(IDIM / 128, NTOK / 128), 512, SMEM_D>>>(
        xh, xl, gwh, nullptr, uwh, nullptr, nullptr, hh, HDIM, IDIM);

    // join expert branch, then down GEMM (pure fp16, 1-product) with fused expert add
    cudaStreamWaitEvent(0, ev2, 0);
    mma_gemm_u<false, false, false, 2, 6><<<dim3(HDIM / 128, NTOK / 128), 512, SMEM_S>>>(
        hh, nullptr, dwh, nullptr, nullptr, eo, out, nullptr, IDIM, HDIM);
}

// round 15
// speedup vs baseline: 1.9794x; 1.2367x over previous
#include <cuda_runtime.h>
#include <cuda_fp16.h>
#include <math.h>
#include <stdint.h>

#define NTOK 4096   // B*S
#define HDIM 1024
#define IDIM 4096
#define NS   128
#define TOPK 16
#define BN_EPS 1e-5f

typedef __half fp16;

// ================= scratch (static device allocations) =================
__device__ float g_rx[NTOK * NS];
__device__ float g_ry[NTOK * NS];
__device__ float g_mean[2 * NS];
__device__ float g_rstd[2 * NS];
__device__ int   g_idx[NTOK * TOPK];
__device__ float g_wk[NTOK * TOPK];
__device__ float g_eout[(size_t)NTOK * HDIM];
// fp16 operands: x hi/lo (router only needs lo); dense weights hi-only; h hi-only.
__device__ fp16 g_xh[NTOK * HDIM],  g_xl[NTOK * HDIM];
__device__ fp16 g_gwh[IDIM * HDIM];
__device__ fp16 g_uwh[IDIM * HDIM];
__device__ fp16 g_dwh[HDIM * IDIM];
__device__ fp16 g_rwxh[NS * HDIM], g_rwxl[NS * HDIM];
__device__ fp16 g_rwyh[NS * HDIM], g_rwyl[NS * HDIM];
__device__ fp16 g_hh[(size_t)NTOK * IDIM];

// ================= helpers =================
__device__ __forceinline__ uint32_t smem_to_u32(const void* p) {
    uint32_t a;
    asm("{ .reg .u64 t; cvta.to.shared.u64 t, %1; cvt.u32.u64 %0, t; }" : "=r"(a) : "l"(p));
    return a;
}

#define MMA16816(c, a, b) \
    asm volatile("mma.sync.aligned.m16n8k16.row.col.f32.f16.f16.f32 " \
        "{%0,%1,%2,%3}, {%4,%5,%6,%7}, {%8,%9}, {%0,%1,%2,%3};" \
        : "+f"((c)[0]), "+f"((c)[1]), "+f"((c)[2]), "+f"((c)[3]) \
        : "r"((a)[0]), "r"((a)[1]), "r"((a)[2]), "r"((a)[3]), "r"((b)[0]), "r"((b)[1]))

#define LDSM_X4(r, addr) \
    asm volatile("ldmatrix.sync.aligned.m8n8.x4.shared.b16 {%0,%1,%2,%3}, [%4];" \
        : "=r"((r)[0]), "=r"((r)[1]), "=r"((r)[2]), "=r"((r)[3]) : "r"(addr))

#define TILE_B 10240   // 128 rows * 80B (32 fp16 + 8B pad), conflict-free for ldmatrix

// ================= unified fp16 split-precision tensor-core GEMM =================
// C[M,N(128)] = A[M,K] * B^T, fp32 accum.
//  AL: A has lo correction (adds al*bh)   -- router only
//  BL: B has lo correction (adds ah*bl)   -- router only (exact top-k)
//  AL=false, BL=false: plain fp16 (dense gate/up/down)
// 512 threads = 16 warps (4x4 of 32x32 warp tiles), 128x128 CTA tile, BK=32,
// NST-stage cp.async pipeline. MODE 0: Cout=acc. MODE 2: Cout=acc+E.
// MODE 1 (DUAL): h=silu(g)*u -> fp16 (hi only).
// Stage tile layout: [Ah, (AL? Al), B1h, (DUAL? B2h : BL? B1l)]

template<bool DUAL, bool BL, bool AL, int MODE, int NST>
__global__ __launch_bounds__(512, 1) void mma_gemm_u(
    const fp16* __restrict__ Ah, const fp16* __restrict__ Al,
    const fp16* __restrict__ B1h, const fp16* __restrict__ B1l,
    const fp16* __restrict__ B2h,
    const float* __restrict__ E, float* __restrict__ Cout,
    fp16* __restrict__ Hh, int K, int ldo)
{
    constexpr int NA = AL ? 2 : 1;
    constexpr int NTILE = NA + 1 + ((DUAL || BL) ? 1 : 0);
    constexpr int STAGE = NTILE * TILE_B;
    constexpr uint32_t OFF_B1 = NA * TILE_B;
    constexpr uint32_t OFF_B2 = OFF_B1 + TILE_B;   // B2h or B1l
    extern __shared__ __align__(128) char smem[];
    const uint32_t sb = smem_to_u32(smem);
    const int tid = threadIdx.x;
    const int lane = tid & 31;
    const int warp = tid >> 5;
    const int warp_m = warp >> 2;      // 0..3
    const int warp_n = warp & 3;       // 0..3
    const int bm = blockIdx.y * 128, bn = blockIdx.x * 128;
    const int KC = K >> 5;

    float accg[2][4][4];
    float accu[2][4][4];
#pragma unroll
    for (int i = 0; i < 2; i++)
#pragma unroll
        for (int j = 0; j < 4; j++)
#pragma unroll
            for (int e = 0; e < 4; e++) { accg[i][j][e] = 0.f; if (DUAL) accu[i][j][e] = 0.f; }

    // 512 threads x 16B = 8KB = exactly one 128x32 fp16 tile per pass
    auto load_stage = [&](int st, int k0) {
        int r = tid >> 2, c = tid & 3;
        uint32_t sa0 = sb + st * STAGE + r * 80 + c * 16;
#pragma unroll
        for (int t = 0; t < NTILE; t++) {
            const fp16* src;
            if (t == 0) src = Ah;
            else if (AL && t == 1) src = Al;
            else if (t == NA) src = B1h;
            else src = DUAL ? B2h : B1l;
            int row0 = (t < NA) ? bm : bn;
            const fp16* ga = src + (size_t)(row0 + r) * K + k0 + c * 8;
            asm volatile("cp.async.cg.shared.global [%0], [%1], 16;"
                         :: "r"(sa0 + t * TILE_B), "l"(ga));
        }
    };

#pragma unroll
    for (int p = 0; p < NST - 1; p++) {
        load_stage(p, p * 32);
        asm volatile("cp.async.commit_group;" ::: "memory");
    }

    int st_c = 0, st_l = NST - 1;
    for (int kc = 0; kc < KC; kc++) {
        asm volatile("cp.async.wait_group %0;" :: "n"(NST - 2) : "memory");
        __syncthreads();
        if (kc + NST - 1 < KC) load_stage(st_l, (kc + NST - 1) * 32);
        asm volatile("cp.async.commit_group;" ::: "memory");

        const uint32_t stage = sb + st_c * STAGE;
#pragma unroll
        for (int kk = 0; kk < 32; kk += 16) {
            uint32_t ah[2][4], al[2][4];
#pragma unroll
            for (int fm = 0; fm < 2; fm++) {
                int row = warp_m * 32 + fm * 16 + (lane & 15);
                int kw = kk + (lane >> 4) * 8;
                uint32_t a_addr = stage + row * 80 + kw * 2;
                LDSM_X4(ah[fm], a_addr);
                if (AL) LDSM_X4(al[fm], a_addr + TILE_B);
            }
            int brow = warp_n * 32 + (lane & 15);
            int bkw = kk + (lane >> 4) * 8;
            // B1
            {
                uint32_t bh[4][2], bl[4][2];
#pragma unroll
                for (int fp = 0; fp < 2; fp++) {
                    uint32_t b_addr = stage + OFF_B1 + (brow + fp * 16) * 80 + bkw * 2;
                    uint32_t th[4];
                    LDSM_X4(th, b_addr);
                    bh[2 * fp][0] = th[0]; bh[2 * fp + 1][0] = th[1];
                    bh[2 * fp][1] = th[2]; bh[2 * fp + 1][1] = th[3];
                    if (BL) {
                        uint32_t tl[4];
                        LDSM_X4(tl, b_addr + TILE_B);
                        bl[2 * fp][0] = tl[0]; bl[2 * fp + 1][0] = tl[1];
                        bl[2 * fp][1] = tl[2]; bl[2 * fp + 1][1] = tl[3];
                    }
                }
#pragma unroll
                for (int fm = 0; fm < 2; fm++)
#pragma unroll
                    for (int fn = 0; fn < 4; fn++) {
                        MMA16816(accg[fm][fn], ah[fm], bh[fn]);
                        if (AL) MMA16816(accg[fm][fn], al[fm], bh[fn]);
                        if (BL) MMA16816(accg[fm][fn], ah[fm], bl[fn]);
                    }
            }
            // B2 (dual only, hi-only)
            if (DUAL) {
                uint32_t bh[4][2];
#pragma unroll
                for (int fp = 0; fp < 2; fp++) {
                    uint32_t b_addr = stage + OFF_B2 + (brow + fp * 16) * 80 + bkw * 2;
                    uint32_t th[4];
                    LDSM_X4(th, b_addr);
                    bh[2 * fp][0] = th[0]; bh[2 * fp + 1][0] = th[1];
                    bh[2 * fp][1] = th[2]; bh[2 * fp + 1][1] = th[3];
                }
#pragma unroll
                for (int fm = 0; fm < 2; fm++)
#pragma unroll
                    for (int fn = 0; fn < 4; fn++) {
                        MMA16816(accu[fm][fn], ah[fm], bh[fn]);
                        if (AL) MMA16816(accu[fm][fn], al[fm], bh[fn]);
                    }
            }
        }
        st_c++; if (st_c == NST) st_c = 0;
        st_l++; if (st_l == NST) st_l = 0;
    }

    // ---------------- epilogue ----------------
#pragma unroll
    for (int fm = 0; fm < 2; fm++)
#pragma unroll
        for (int fn = 0; fn < 4; fn++) {
            int row = bm + warp_m * 32 + fm * 16 + (lane >> 2);
            int col = bn + warp_n * 32 + fn * 8 + 2 * (lane & 3);
#pragma unroll
            for (int h = 0; h < 2; h++) {
                int r = row + h * 8;
                size_t off = (size_t)r * ldo + col;
                float d0 = accg[fm][fn][2 * h], d1 = accg[fm][fn][2 * h + 1];
                if (MODE == 1) {
                    float ux = accu[fm][fn][2 * h], uy = accu[fm][fn][2 * h + 1];
                    float h0 = d0 / (1.f + expf(-d0)) * ux;
                    float h1 = d1 / (1.f + expf(-d1)) * uy;
                    *(__half2*)(Hh + off) =
                        __halves2half2(__float2half_rn(h0), __float2half_rn(h1));
                } else {
                    if (MODE == 2) {
                        float2 e = *(const float2*)(E + off);
                        d0 += e.x; d1 += e.y;
                    }
                    *(float2*)(Cout + off) = make_float2(d0, d1);
                }
            }
        }
}

// ================= fp32 -> fp16 hi/lo split =================
__global__ void split2_kernel(const float* __restrict__ s, fp16* __restrict__ hi,
                              fp16* __restrict__ lo, int n4)
{
    int i = blockIdx.x * blockDim.x + threadIdx.x;
    if (i >= n4) return;
    float4 v = ((const float4*)s)[i];
    float vv[4] = {v.x, v.y, v.z, v.w};
    fp16 h[4], l[4];
#pragma unroll
    for (int j = 0; j < 4; j++) {
        h[j] = __float2half_rn(vv[j]);
        l[j] = __float2half_rn(vv[j] - __half2float(h[j]));
    }
    ((__half2*)hi)[2 * i]     = __halves2half2(h[0], h[1]);
    ((__half2*)hi)[2 * i + 1] = __halves2half2(h[2], h[3]);
    ((__half2*)lo)[2 * i]     = __halves2half2(l[0], l[1]);
    ((__half2*)lo)[2 * i + 1] = __halves2half2(l[2], l[3]);
}

// ================= fp32 -> fp16 (hi only, for dense weights) =================
__global__ void conv1_kernel(const float* __restrict__ s, fp16* __restrict__ hi, int n4)
{
    int i = blockIdx.x * blockDim.x + threadIdx.x;
    if (i >= n4) return;
    float4 v = ((const float4*)s)[i];
    ((__half2*)hi)[2 * i]     = __halves2half2(__float2half_rn(v.x), __float2half_rn(v.y));
    ((__half2*)hi)[2 * i + 1] = __halves2half2(__float2half_rn(v.z), __float2half_rn(v.w));
}

// ================= batch stats =================
__global__ void col_stats()
{
    const int c = blockIdx.x;
    const float* r = (c < NS) ? g_rx : g_ry;
    const int col = c & (NS - 1);
    float s = 0.f, s2 = 0.f;
    for (int i = threadIdx.x; i < NTOK; i += 256) {
        float v = r[i * NS + col];
        s += v; s2 += v * v;
    }
    __shared__ float sh[64];
#pragma unroll
    for (int o = 16; o; o >>= 1) {
        s  += __shfl_down_sync(0xffffffffu, s,  o);
        s2 += __shfl_down_sync(0xffffffffu, s2, o);
    }
    const int w = threadIdx.x >> 5;
    if ((threadIdx.x & 31) == 0) { sh[w] = s; sh[32 + w] = s2; }
    __syncthreads();
    if (threadIdx.x == 0) {
        float S = 0.f, S2 = 0.f;
        for (int i = 0; i < 8; i++) { S += sh[i]; S2 += sh[32 + i]; }
        float m = S / (float)NTOK;
        float var = S2 / (float)NTOK - m * m;
        g_mean[c] = m;
        g_rstd[c] = rsqrtf(var + BN_EPS);
    }
}

// ================= bn + log_softmax =================
__global__ void bn_logsoftmax()
{
    const int n = blockIdx.x;
    const int c = threadIdx.x;
    __shared__ float sh[4];
#pragma unroll
    for (int r = 0; r < 2; r++) {
        float* buf = r ? g_ry : g_rx;
        float z = (buf[n * NS + c] - g_mean[r * NS + c]) * g_rstd[r * NS + c];
        float v = z;
#pragma unroll
        for (int o = 16; o; o >>= 1) v = fmaxf(v, __shfl_xor_sync(0xffffffffu, v, o));
        if ((c & 31) == 0) sh[c >> 5] = v;
        __syncthreads();
        float m = fmaxf(fmaxf(sh[0], sh[1]), fmaxf(sh[2], sh[3]));
        __syncthreads();
        float e = expf(z - m), sv = e;
#pragma unroll
        for (int o = 16; o; o >>= 1) sv += __shfl_xor_sync(0xffffffffu, sv, o);
        if ((c & 31) == 0) sh[c >> 5] = sv;
        __syncthreads();
        float tot = sh[0] + sh[1] + sh[2] + sh[3];
        buf[n * NS + c] = z - (m + logf(tot));
        __syncthreads();
    }
}

// ================= product-key top-k =================
__global__ void topk_kernel()
{
    const int n = blockIdx.x;
    const int lane = threadIdx.x;
    __shared__ float sx[16], sy[16];
    __shared__ int sxi[16], syi[16];
    const float* rowx = g_rx + n * NS;
    const float* rowy = g_ry + n * NS;
    float vx[4], vy[4];
#pragma unroll
    for (int j = 0; j < 4; j++) { vx[j] = rowx[lane * 4 + j]; vy[j] = rowy[lane * 4 + j]; }

    for (int t = 0; t < 16; t++) {
        float bv = -INFINITY; int bj = 0;
#pragma unroll
        for (int j = 0; j < 4; j++) if (vx[j] > bv) { bv = vx[j]; bj = j; }
        int bl = lane;
#pragma unroll
        for (int o = 16; o; o >>= 1) {
            float ov = __shfl_down_sync(0xffffffffu, bv, o);
            int ol = __shfl_down_sync(0xffffffffu, bl, o);
            int oj = __shfl_down_sync(0xffffffffu, bj, o);
            if (ov > bv) { bv = ov; bl = ol; bj = oj; }
        }
        bv = __shfl_sync(0xffffffffu, bv, 0);
        bl = __shfl_sync(0xffffffffu, bl, 0);
        bj = __shfl_sync(0xffffffffu, bj, 0);
        if (lane == bl) {
#pragma unroll
            for (int j = 0; j < 4; j++) if (j == bj) vx[j] = -INFINITY;
        }
        if (lane == 0) { sx[t] = bv; sxi[t] = bl * 4 + bj; }
    }
    for (int t = 0; t < 16; t++) {
        float bv = -INFINITY; int bj = 0;
#pragma unroll
        for (int j = 0; j < 4; j++) if (vy[j] > bv) { bv = vy[j]; bj = j; }
        int bl = lane;
#pragma unroll
        for (int o = 16; o; o >>= 1) {
            float ov = __shfl_down_sync(0xffffffffu, bv, o);
            int ol = __shfl_down_sync(0xffffffffu, bl, o);
            int oj = __shfl_down_sync(0xffffffffu, bj, o);
            if (ov > bv) { bv = ov; bl = ol; bj = oj; }
        }
        bv = __shfl_sync(0xffffffffu, bv, 0);
        bl = __shfl_sync(0xffffffffu, bl, 0);
        bj = __shfl_sync(0xffffffffu, bj, 0);
        if (lane == bl) {
#pragma unroll
            for (int j = 0; j < 4; j++) if (j == bj) vy[j] = -INFINITY;
        }
        if (lane == 0) { sy[t] = bv; syi[t] = bl * 4 + bj; }
    }
    __syncwarp();

    float cv[8];
#pragma unroll
    for (int j = 0; j < 8; j++) {
        int p = lane * 8 + j;
        cv[j] = sx[p >> 4] + sy[p & 15];
    }
    for (int t = 0; t < 16; t++) {
        float bv = -INFINITY; int bj = 0;
#pragma unroll
        for (int j = 0; j < 8; j++) if (cv[j] > bv) { bv = cv[j]; bj = j; }
        int bl = lane;
#pragma unroll
        for (int o = 16; o; o >>= 1) {
            float ov = __shfl_down_sync(0xffffffffu, bv, o);
            int ol = __shfl_down_sync(0xffffffffu, bl, o);
            int oj = __shfl_down_sync(0xffffffffu, bj, o);
            if (ov > bv) { bv = ov; bl = ol; bj = oj; }
        }
        bv = __shfl_sync(0xffffffffu, bv, 0);
        bl = __shfl_sync(0xffffffffu, bl, 0);
        bj = __shfl_sync(0xffffffffu, bj, 0);
        if (lane == bl) {
#pragma unroll
            for (int j = 0; j < 8; j++) if (j == bj) cv[j] = -INFINITY;
        }
        if (lane == 0) {
            int p = bl * 8 + bj;
            g_idx[n * TOPK + t] = sxi[p >> 4] * NS + syi[p & 15];
            g_wk[n * TOPK + t] = expf(bv);
        }
    }
}

// ================= expert gather (writes g_eout) =================
__global__ __launch_bounds__(256) void expert_kernel(
    const float* __restrict__ x,
    const float* __restrict__ up_e,
    const float* __restrict__ down_e)
{
    const int n = blockIdx.x;
    __shared__ float sx[HDIM];
    __shared__ float sew[TOPK];
    const int tid = threadIdx.x;
    for (int i = tid; i < HDIM; i += 256) sx[i] = x[(size_t)n * HDIM + i];
    __syncthreads();
    const int warp = tid >> 5, lane = tid & 31;
#pragma unroll
    for (int k = warp; k < TOPK; k += 8) {
        int e = g_idx[n * TOPK + k];
        const float* ue = up_e + (size_t)e * HDIM;
        float d = 0.f;
#pragma unroll
        for (int i = lane * 4; i < HDIM; i += 128) {
            float4 u = *(const float4*)(ue + i);
            d += u.x * sx[i] + u.y * sx[i + 1] + u.z * sx[i + 2] + u.w * sx[i + 3];
        }
#pragma unroll
        for (int o = 16; o; o >>= 1) d += __shfl_down_sync(0xffffffffu, d, o);
        if (lane == 0) {
            float s = d / (1.f + expf(-d));
            sew[k] = s * g_wk[n * TOPK + k];
        }
    }
    __syncthreads();
    float acc[4] = {0.f, 0.f, 0.f, 0.f};
#pragma unroll
    for (int k = 0; k < TOPK; k++) {
        int e = g_idx[n * TOPK + k];
        float wk = sew[k];
        const float* de = down_e + (size_t)e * HDIM;
#pragma unroll
        for (int j = 0; j < 4; j++) acc[j] += wk * de[tid + j * 256];
    }
#pragma unroll
    for (int j = 0; j < 4; j++)
        g_eout[(size_t)n * HDIM + tid + j * 256] = acc[j];
}

// ================= launch =================
extern "C" void kernel_launch(void* const* d_in, const int* in_sizes, int n_in,
                              void* d_out, int out_size)
{
    const float* x      = (const float*)d_in[0];
    const float* gate_w = (const float*)d_in[1];
    const float* up_w   = (const float*)d_in[2];
    const float* down_w = (const float*)d_in[3];
    const float* rxw    = (const float*)d_in[4];
    const float* ryw    = (const float*)d_in[5];
    const float* up_e   = (const float*)d_in[6];
    const float* down_e = (const float*)d_in[7];
    float* out = (float*)d_out;

    float *rx, *ry, *eo;
    cudaGetSymbolAddress((void**)&rx, g_rx);
    cudaGetSymbolAddress((void**)&ry, g_ry);
    cudaGetSymbolAddress((void**)&eo, g_eout);
    fp16 *xh, *xl, *gwh, *uwh, *dwh, *hh;
    fp16 *rwxh, *rwxl, *rwyh, *rwyl;
    cudaGetSymbolAddress((void**)&xh, g_xh);   cudaGetSymbolAddress((void**)&xl, g_xl);
    cudaGetSymbolAddress((void**)&gwh, g_gwh);
    cudaGetSymbolAddress((void**)&uwh, g_uwh);
    cudaGetSymbolAddress((void**)&dwh, g_dwh);
    cudaGetSymbolAddress((void**)&rwxh, g_rwxh); cudaGetSymbolAddress((void**)&rwxl, g_rwxl);
    cudaGetSymbolAddress((void**)&rwyh, g_rwyh); cudaGetSymbolAddress((void**)&rwyl, g_rwyl);
    cudaGetSymbolAddress((void**)&hh, g_hh);

    const int SMEM_R = 4 * 4 * TILE_B;   // router: 4 tiles x 4 stages = 163840
    const int SMEM_D = 5 * 3 * TILE_B;   // dual:   3 tiles x 5 stages = 153600
    const int SMEM_S = 6 * 2 * TILE_B;   // down:   2 tiles x 6 stages = 122880
    static cudaStream_t s2 = nullptr, s3 = nullptr;
    static cudaEvent_t ev0 = nullptr, ev1 = nullptr, ev2 = nullptr, ev3 = nullptr;
    if (!s2) {
        cudaFuncSetAttribute((const void*)mma_gemm_u<false, true,  true,  0, 4>, cudaFuncAttributeMaxDynamicSharedMemorySize, SMEM_R);
        cudaFuncSetAttribute((const void*)mma_gemm_u<true,  false, false, 1, 5>, cudaFuncAttributeMaxDynamicSharedMemorySize, SMEM_D);
        cudaFuncSetAttribute((const void*)mma_gemm_u<false, false, false, 2, 6>, cudaFuncAttributeMaxDynamicSharedMemorySize, SMEM_S);
        cudaStreamCreateWithFlags(&s2, cudaStreamNonBlocking);
        cudaStreamCreateWithFlags(&s3, cudaStreamNonBlocking);
        cudaEventCreateWithFlags(&ev0, cudaEventDisableTiming);
        cudaEventCreateWithFlags(&ev1, cudaEventDisableTiming);
        cudaEventCreateWithFlags(&ev2, cudaEventDisableTiming);
        cudaEventCreateWithFlags(&ev3, cudaEventDisableTiming);
    }

    int n4 = NTOK * HDIM / 4;
    int w4 = IDIM * HDIM / 4;
    int r4 = NS * HDIM / 4;

    // ---- fork s3 from the capture stream FIRST (capture-legal), then its work ----
    cudaEventRecord(ev0, 0);
    cudaStreamWaitEvent(s3, ev0, 0);
    conv1_kernel<<<(w4 + 255) / 256, 256, 0, s3>>>(gate_w, gwh, w4);
    conv1_kernel<<<(w4 + 255) / 256, 256, 0, s3>>>(up_w,   uwh, w4);
    cudaEventRecord(ev3, s3);

    // ---- main stream: x split (hi for dense; lo used by router) ----
    split2_kernel<<<(n4 + 255) / 256, 256>>>(x, xh, xl, n4);
    cudaEventRecord(ev1, 0);
    cudaStreamWaitEvent(s2, ev1, 0);

    // ---- side stream s2: down_w conv + router chain + expert gather ----
    conv1_kernel<<<(w4 + 255) / 256, 256, 0, s2>>>(down_w, dwh, w4);
    split2_kernel<<<(r4 + 255) / 256, 256, 0, s2>>>(rxw, rwxh, rwxl, r4);
    split2_kernel<<<(r4 + 255) / 256, 256, 0, s2>>>(ryw, rwyh, rwyl, r4);
    mma_gemm_u<false, true, true, 0, 4><<<dim3(1, NTOK / 128), 512, SMEM_R, s2>>>(
        xh, xl, rwxh, rwxl, nullptr, nullptr, rx, nullptr, HDIM, NS);
    mma_gemm_u<false, true, true, 0, 4><<<dim3(1, NTOK / 128), 512, SMEM_R, s2>>>(
        xh, xl, rwyh, rwyl, nullptr, nullptr, ry, nullptr, HDIM, NS);
    col_stats<<<2 * NS, 256, 0, s2>>>();
    bn_logsoftmax<<<NTOK, NS, 0, s2>>>();
    topk_kernel<<<NTOK, 32, 0, s2>>>();
    expert_kernel<<<NTOK, 256, 0, s2>>>(x, up_e, down_e);
    cudaEventRecord(ev2, s2);

    // ---- main stream: dense MLP ----
    cudaStreamWaitEvent(0, ev3, 0);
    // fused gate+up (pure fp16, 1-product each) -> h (fp16 hi only)
    mma_gemm_u<true, false, false, 1, 5><<<dim3(IDIM / 128, NTOK / 128), 512, SMEM_D>>>(
        xh, nullptr, gwh, nullptr, uwh, nullptr, nullptr, hh, HDIM, IDIM);

    // join expert branch, then down GEMM (pure fp16, 1-product) with fused expert add
    cudaStreamWaitEvent(0, ev2, 0);
    mma_gemm_u<false, false, false, 2, 6><<<dim3(HDIM / 128, NTOK / 128), 512, SMEM_S>>>(
        hh, nullptr, dwh, nullptr, nullptr, eo, out, nullptr, IDIM, HDIM);
}